// round 10
// baseline (speedup 1.0000x reference)
#include <cuda_runtime.h>
#include <cuda_bf16.h>
#include <math.h>
#include <stdint.h>

#define BB   32
#define DD   768
#define NHD  12
#define HD   64
#define NMAX 197
#define LMAX 196
#define ATTN_SCALE 0.125f

typedef __nv_bfloat16 bf16;

// ---------------- weight pair sizes ----------------
#define SZ_QKVW  (12*2304*768)
#define SZ_PROJW (12*768*768)
#define SZ_FC1W  (12*3072*768)
#define SZ_FC2W  (12*3072*768)
#define SZ_PATCHW (768*768)
#define SZ_PINW  (3*768*768)
#define SZ_PW1   (3*384*768)
#define SZ_PW2   (3*192*384)

// ---------------- scratch (device globals; no allocation allowed) ----------------
__device__ float g_t0[BB*NMAX*DD];
__device__ float g_t1[BB*NMAX*DD];
__device__ float g_qkv[BB*NMAX*2304];
__device__ float g_pa[BB*LMAX*DD];
__device__ float g_pb[BB*LMAX*DD];
__device__ float g_glob[BB*384];
__device__ float g_score[BB*LMAX];
__device__ int   g_idx[BB*LMAX];
__device__ float g_cls[BB*DD];
__device__ float g_att[(size_t)BB*NHD*NMAX*NMAX];

// bf16 hi/lo activation pairs
__device__ bf16 g_lnh[BB*NMAX*DD],  g_lnl[BB*NMAX*DD];
__device__ bf16 g_aoh[BB*NMAX*DD],  g_aol[BB*NMAX*DD];
__device__ bf16 g_mlph[BB*NMAX*3072], g_mlpl[BB*NMAX*3072];
__device__ bf16 g_imh[BB*LMAX*DD],  g_iml[BB*LMAX*DD];
__device__ bf16 g_ppbh[BB*LMAX*384], g_ppbl[BB*LMAX*384];

// bf16 hi/lo weight pairs
__device__ bf16 g_qkvwh[SZ_QKVW],  g_qkvwl[SZ_QKVW];
__device__ bf16 g_projwh[SZ_PROJW], g_projwl[SZ_PROJW];
__device__ bf16 g_fc1wh[SZ_FC1W],  g_fc1wl[SZ_FC1W];
__device__ bf16 g_fc2wh[SZ_FC2W],  g_fc2wl[SZ_FC2W];
__device__ bf16 g_patchwh[SZ_PATCHW], g_patchwl[SZ_PATCHW];
__device__ bf16 g_pinwh[SZ_PINW],  g_pinwl[SZ_PINW];
__device__ bf16 g_pw1h[SZ_PW1],    g_pw1l[SZ_PW1];
__device__ bf16 g_pw2h[SZ_PW2],    g_pw2l[SZ_PW2];

__device__ __forceinline__ float gelu_f(float x) {
    return 0.5f * x * (1.f + erff(x * 0.70710678118654752440f));
}

__device__ __forceinline__ void split1(float v, bf16& h, bf16& l) {
    h = __float2bfloat16(v);
    l = __float2bfloat16(v - __bfloat162float(h));
}

// split two floats into packed bf16 hi pair + lo pair
__device__ __forceinline__ void split2_bf16(float v0, float v1, uint32_t& hi, uint32_t& lo) {
    bf16 h0 = __float2bfloat16(v0);
    bf16 h1 = __float2bfloat16(v1);
    float r0 = v0 - __bfloat162float(h0);
    float r1 = v1 - __bfloat162float(h1);
    bf16 l0 = __float2bfloat16(r0);
    bf16 l1 = __float2bfloat16(r1);
    hi = (uint32_t)__bfloat16_as_ushort(h0) | ((uint32_t)__bfloat16_as_ushort(h1) << 16);
    lo = (uint32_t)__bfloat16_as_ushort(l0) | ((uint32_t)__bfloat16_as_ushort(l1) << 16);
}

// ---------------- weight split: fp32 -> bf16 hi/lo pairs ----------------
__global__ void split_kernel(const float* __restrict__ in, bf16* __restrict__ hi,
                             bf16* __restrict__ lo, int n4)
{
    int i = blockIdx.x * blockDim.x + threadIdx.x;
    if (i >= n4) return;
    float4 v = ((const float4*)in)[i];
    uint32_t h0, l0, h1, l1;
    split2_bf16(v.x, v.y, h0, l0);
    split2_bf16(v.z, v.w, h1, l1);
    ((uint32_t*)hi)[i*2]   = h0;
    ((uint32_t*)hi)[i*2+1] = h1;
    ((uint32_t*)lo)[i*2]   = l0;
    ((uint32_t*)lo)[i*2+1] = l1;
}

// ---------------- im2col for patch embedding (writes bf16 pair) ----------------
__global__ void im2col_kernel(const float* __restrict__ x, bf16* __restrict__ ph,
                              bf16* __restrict__ pl) {
    int i = blockIdx.x * blockDim.x + threadIdx.x;
    const int total = BB*LMAX*DD;
    if (i >= total) return;
    int c = i % DD;
    int r = i / DD;
    int b = r / LMAX;
    int l = r % LMAX;
    int gy = l / 14, gx = l % 14;
    int ch = c / 256, rem = c % 256, py = rem / 16, px = rem % 16;
    float v = x[(((size_t)b*3 + ch)*224 + gy*16 + py)*224 + gx*16 + px];
    split1(v, ph[i], pl[i]);
}

// assemble t = [cls | patches] + pos
__global__ void assemble_kernel(const float* __restrict__ pe, const float* __restrict__ cls,
                                const float* __restrict__ pos, float* __restrict__ t) {
    int i = blockIdx.x * blockDim.x + threadIdx.x;
    const int total = BB*NMAX*DD;
    if (i >= total) return;
    int d = i % DD;
    int n = (i / DD) % NMAX;
    int b = i / (DD*NMAX);
    float v = (n == 0) ? cls[d] : pe[((size_t)b*LMAX + (n-1))*DD + d];
    t[i] = v + pos[n*DD + d];
}

// =====================================================================
// mma helpers
// =====================================================================
#define SK 20   // smem row stride (words): conflict-free frag loads

__device__ __forceinline__ uint32_t f2tf(float f) {
    uint32_t u;
    asm("cvt.rna.tf32.f32 %0, %1;" : "=r"(u) : "f"(f));
    return u;
}

__device__ __forceinline__ void mma_tf32(float d[4], const uint32_t a[4], const uint32_t b[2]) {
    asm volatile(
        "mma.sync.aligned.m16n8k8.row.col.f32.tf32.tf32.f32 "
        "{%0,%1,%2,%3}, {%4,%5,%6,%7}, {%8,%9}, {%0,%1,%2,%3};\n"
        : "+f"(d[0]), "+f"(d[1]), "+f"(d[2]), "+f"(d[3])
        : "r"(a[0]), "r"(a[1]), "r"(a[2]), "r"(a[3]), "r"(b[0]), "r"(b[1]));
}

__device__ __forceinline__ void mma_bf16(float d[4], const uint32_t a[4], const uint32_t b[2]) {
    asm volatile(
        "mma.sync.aligned.m16n8k16.row.col.f32.bf16.bf16.f32 "
        "{%0,%1,%2,%3}, {%4,%5,%6,%7}, {%8,%9}, {%0,%1,%2,%3};\n"
        : "+f"(d[0]), "+f"(d[1]), "+f"(d[2]), "+f"(d[3])
        : "r"(a[0]), "r"(a[1]), "r"(a[2]), "r"(a[3]), "r"(b[0]), "r"(b[1]));
}

// =====================================================================
// Tensor-core GEMM v2: C = act(A[M,K] @ W[N,K]^T + bias) (+resid)
// A and W are pre-split bf16 hi/lo pairs; loader is a pure copy.
// 128x128x16 CTA tile, 256 threads, warp grid 2x4, warp tile 64x32.
// Output: fp32 (Cf) or bf16 pair (Ch/Cl).
// =====================================================================
__global__ __launch_bounds__(256)
void gemm_tc2_kernel(const bf16* __restrict__ Ahg, const bf16* __restrict__ Alg,
                     const bf16* __restrict__ Whg, const bf16* __restrict__ Wlg,
                     const float* __restrict__ bias, const float* __restrict__ resid,
                     float* __restrict__ Cf, bf16* __restrict__ Ch, bf16* __restrict__ Cl,
                     int M, int N, int K, int act)
{
    __shared__ __align__(16) uint32_t Ah[128][SK];
    __shared__ __align__(16) uint32_t Al[128][SK];
    __shared__ __align__(16) uint32_t Bh[128][SK];
    __shared__ __align__(16) uint32_t Bl[128][SK];

    int tid = threadIdx.x;
    int lane = tid & 31, w = tid >> 5;
    int wm = w >> 2, wn = w & 3;          // warp grid 2x4
    int g = lane >> 2, tig = lane & 3;    // mma quad coords
    int row0 = blockIdx.y * 128, col0 = blockIdx.x * 128;

    float acc[4][4][4];
    #pragma unroll
    for (int i = 0; i < 4; i++)
        #pragma unroll
        for (int j = 0; j < 4; j++)
            #pragma unroll
            for (int q = 0; q < 4; q++) acc[i][j][q] = 0.f;

    int lr = tid & 127;           // tile row 0..127
    int le = (tid >> 7) * 8;      // element col offset: 0 or 8
    int lw = (tid >> 7) * 4;      // smem word col: 0 or 4

    const uint4 z4 = make_uint4(0u, 0u, 0u, 0u);
    uint4 pAh, pAl, pBh, pBl;

    // initial prefetch (k0 = 0)
    {
        int gr = row0 + lr;
        pAh = (gr < M) ? *(const uint4*)(Ahg + (size_t)gr*K + le) : z4;
        pAl = (gr < M) ? *(const uint4*)(Alg + (size_t)gr*K + le) : z4;
        int wr = col0 + lr;
        pBh = (wr < N) ? *(const uint4*)(Whg + (size_t)wr*K + le) : z4;
        pBl = (wr < N) ? *(const uint4*)(Wlg + (size_t)wr*K + le) : z4;
    }

    int ktiles = K >> 4;
    for (int kt = 0; kt < ktiles; kt++) {
        *(uint4*)&Ah[lr][lw] = pAh;
        *(uint4*)&Al[lr][lw] = pAl;
        *(uint4*)&Bh[lr][lw] = pBh;
        *(uint4*)&Bl[lr][lw] = pBl;
        __syncthreads();

        // prefetch next tile (overlaps with mma below)
        if (kt + 1 < ktiles) {
            int k0 = (kt + 1) << 4;
            int gr = row0 + lr;
            pAh = (gr < M) ? *(const uint4*)(Ahg + (size_t)gr*K + k0 + le) : z4;
            pAl = (gr < M) ? *(const uint4*)(Alg + (size_t)gr*K + k0 + le) : z4;
            int wr = col0 + lr;
            pBh = (wr < N) ? *(const uint4*)(Whg + (size_t)wr*K + k0 + le) : z4;
            pBl = (wr < N) ? *(const uint4*)(Wlg + (size_t)wr*K + k0 + le) : z4;
        }

        // compute: one m16n8k16 covers the whole 16-wide k tile
        {
            uint32_t bhf[4][2], blf[4][2];
            #pragma unroll
            for (int nt = 0; nt < 4; nt++) {
                int n = wn*32 + nt*8 + g;
                bhf[nt][0] = Bh[n][tig];
                bhf[nt][1] = Bh[n][tig+4];
                blf[nt][0] = Bl[n][tig];
                blf[nt][1] = Bl[n][tig+4];
            }
            #pragma unroll
            for (int mt = 0; mt < 4; mt++) {
                int r = wm*64 + mt*16 + g;
                uint32_t ah[4], al[4];
                ah[0] = Ah[r][tig];
                ah[1] = Ah[r+8][tig];
                ah[2] = Ah[r][tig+4];
                ah[3] = Ah[r+8][tig+4];
                al[0] = Al[r][tig];
                al[1] = Al[r+8][tig];
                al[2] = Al[r][tig+4];
                al[3] = Al[r+8][tig+4];
                #pragma unroll
                for (int nt = 0; nt < 4; nt++) {
                    mma_bf16(acc[mt][nt], al, bhf[nt]);   // lo*hi
                    mma_bf16(acc[mt][nt], ah, blf[nt]);   // hi*lo
                    mma_bf16(acc[mt][nt], ah, bhf[nt]);   // hi*hi
                }
            }
        }
        __syncthreads();
    }

    // epilogue
    #pragma unroll
    for (int mt = 0; mt < 4; mt++) {
        #pragma unroll
        for (int nt = 0; nt < 4; nt++) {
            int gc0 = col0 + wn*32 + nt*8 + 2*tig;
            #pragma unroll
            for (int half = 0; half < 2; half++) {
                int gr = row0 + wm*64 + mt*16 + g + half*8;
                if (gr >= M) continue;
                if (Cf) {
                    #pragma unroll
                    for (int j = 0; j < 2; j++) {
                        int gc = gc0 + j;
                        if (gc >= N) continue;
                        float v = acc[mt][nt][half*2 + j] + bias[gc];
                        if (act == 1) v = gelu_f(v);
                        if (resid) v += resid[(size_t)gr*N + gc];
                        Cf[(size_t)gr*N + gc] = v;
                    }
                } else {
                    if (gc0 + 1 >= N) continue;
                    float v0 = acc[mt][nt][half*2 + 0] + bias[gc0];
                    float v1 = acc[mt][nt][half*2 + 1] + bias[gc0+1];
                    if (act == 1) { v0 = gelu_f(v0); v1 = gelu_f(v1); }
                    uint32_t hw, lw2;
                    split2_bf16(v0, v1, hw, lw2);
                    *(uint32_t*)(Ch + (size_t)gr*N + gc0) = hw;
                    *(uint32_t*)(Cl + (size_t)gr*N + gc0) = lw2;
                }
            }
        }
    }
}

// =====================================================================
// Batched attention, stage 1: scores = Q @ K^T per (b,h). 3xTF32.
// =====================================================================
__global__ __launch_bounds__(256)
void attn_qk_kernel(const float* __restrict__ qkv, float* __restrict__ att, int N)
{
    __shared__ __align__(16) float Ah[64][SK];
    __shared__ __align__(16) float Al[64][SK];
    __shared__ __align__(16) float Bh[64][SK];
    __shared__ __align__(16) float Bl[64][SK];

    int tid = threadIdx.x;
    int lane = tid & 31, w = tid >> 5;
    int wm = w >> 2, wn = w & 3;
    int g = lane >> 2, tig = lane & 3;
    int bh = blockIdx.z;
    int b = bh / NHD, h = bh % NHD;
    const float* Q  = qkv + (size_t)b*N*2304 + h*HD;
    const float* Kp = qkv + (size_t)b*N*2304 + 768 + h*HD;
    float* C = att + (size_t)bh*N*N;
    int row0 = blockIdx.y * 64, col0 = blockIdx.x * 64;

    float acc[2][2][4];
    #pragma unroll
    for (int i = 0; i < 2; i++)
        #pragma unroll
        for (int j = 0; j < 2; j++)
            #pragma unroll
            for (int q = 0; q < 4; q++) acc[i][j][q] = 0.f;

    int ldr = tid >> 2;
    int ldc = (tid & 3) * 4;
    const float4 z4 = make_float4(0.f, 0.f, 0.f, 0.f);

    #pragma unroll
    for (int kt = 0; kt < 4; kt++) {
        int k0 = kt * 16;
        {
            int gr = row0 + ldr;
            float4 va = (gr < N) ? *(const float4*)(Q + (size_t)gr*2304 + k0 + ldc) : z4;
            int wr = col0 + ldr;
            float4 vb = (wr < N) ? *(const float4*)(Kp + (size_t)wr*2304 + k0 + ldc) : z4;
            float av[4] = {va.x, va.y, va.z, va.w};
            float bv[4] = {vb.x, vb.y, vb.z, vb.w};
            float4 ah4, al4, bh4, bl4;
            float* ahp = &ah4.x; float* alp = &al4.x;
            float* bhp = &bh4.x; float* blp = &bl4.x;
            #pragma unroll
            for (int j = 0; j < 4; j++) {
                uint32_t hh = f2tf(av[j]);
                ahp[j] = __uint_as_float(hh);
                alp[j] = av[j] - ahp[j];
                uint32_t hb = f2tf(bv[j]);
                bhp[j] = __uint_as_float(hb);
                blp[j] = bv[j] - bhp[j];
            }
            *(float4*)&Ah[ldr][ldc] = ah4;
            *(float4*)&Al[ldr][ldc] = al4;
            *(float4*)&Bh[ldr][ldc] = bh4;
            *(float4*)&Bl[ldr][ldc] = bl4;
        }
        __syncthreads();
        #pragma unroll
        for (int ks = 0; ks < 2; ks++) {
            int k = ks*8 + tig;
            uint32_t bhf[2][2], blf[2][2];
            #pragma unroll
            for (int nt = 0; nt < 2; nt++) {
                int n = wn*16 + nt*8 + g;
                bhf[nt][0] = __float_as_uint(Bh[n][k]);
                bhf[nt][1] = __float_as_uint(Bh[n][k+4]);
                blf[nt][0] = __float_as_uint(Bl[n][k]);
                blf[nt][1] = __float_as_uint(Bl[n][k+4]);
            }
            #pragma unroll
            for (int mt = 0; mt < 2; mt++) {
                int r = wm*32 + mt*16 + g;
                uint32_t ah[4], al[4];
                ah[0] = __float_as_uint(Ah[r][k]);
                ah[1] = __float_as_uint(Ah[r+8][k]);
                ah[2] = __float_as_uint(Ah[r][k+4]);
                ah[3] = __float_as_uint(Ah[r+8][k+4]);
                al[0] = __float_as_uint(Al[r][k]);
                al[1] = __float_as_uint(Al[r+8][k]);
                al[2] = __float_as_uint(Al[r][k+4]);
                al[3] = __float_as_uint(Al[r+8][k+4]);
                #pragma unroll
                for (int nt = 0; nt < 2; nt++) {
                    mma_tf32(acc[mt][nt], al, bhf[nt]);
                    mma_tf32(acc[mt][nt], ah, blf[nt]);
                    mma_tf32(acc[mt][nt], ah, bhf[nt]);
                }
            }
        }
        __syncthreads();
    }

    #pragma unroll
    for (int mt = 0; mt < 2; mt++) {
        #pragma unroll
        for (int nt = 0; nt < 2; nt++) {
            int gc0 = col0 + wn*16 + nt*8 + 2*tig;
            #pragma unroll
            for (int half = 0; half < 2; half++) {
                int gr = row0 + wm*32 + mt*16 + g + half*8;
                if (gr >= N) continue;
                #pragma unroll
                for (int j = 0; j < 2; j++) {
                    int gc = gc0 + j;
                    if (gc < N) C[(size_t)gr*N + gc] = acc[mt][nt][half*2 + j];
                }
            }
        }
    }
}

// =====================================================================
// Batched attention, stage 2: in-place row softmax of scaled scores.
// =====================================================================
__global__ void attn_softmax_kernel(float* __restrict__ att, int N, int rows)
{
    int row = blockIdx.x * 4 + (threadIdx.x >> 5);
    if (row >= rows) return;
    int lane = threadIdx.x & 31;
    float* p = att + (size_t)row * N;
    float v[7];
    int cnt = 0;
    float m = -1e30f;
    for (int j = lane; j < N; j += 32) { float s = p[j]; v[cnt++] = s; m = fmaxf(m, s); }
    #pragma unroll
    for (int o = 16; o > 0; o >>= 1) m = fmaxf(m, __shfl_xor_sync(0xffffffffu, m, o));
    float sum = 0.f;
    #pragma unroll
    for (int q = 0; q < 7; q++) {
        if (q < cnt) { v[q] = expf((v[q] - m) * ATTN_SCALE); sum += v[q]; }
    }
    #pragma unroll
    for (int o = 16; o > 0; o >>= 1) sum += __shfl_xor_sync(0xffffffffu, sum, o);
    float inv = 1.f / sum;
    cnt = 0;
    for (int j = lane; j < N; j += 32) p[j] = v[cnt++] * inv;
}

// =====================================================================
// Batched attention, stage 3: O = P @ V per (b,h). Writes bf16 pair.
// =====================================================================
__global__ __launch_bounds__(256)
void attn_pv_kernel(const float* __restrict__ att, const float* __restrict__ qkv,
                    bf16* __restrict__ oh, bf16* __restrict__ ol, int N)
{
    __shared__ __align__(16) float Ph[64][SK];
    __shared__ __align__(16) float Pl[64][SK];
    __shared__ __align__(16) float Vh[64][SK];   // [d][j]
    __shared__ __align__(16) float Vl[64][SK];

    int tid = threadIdx.x;
    int lane = tid & 31, w = tid >> 5;
    int wm = w >> 2, wn = w & 3;
    int g = lane >> 2, tig = lane & 3;
    int bh = blockIdx.z;
    int b = bh / NHD, h = bh % NHD;
    const float* P = att + (size_t)bh*N*N;
    const float* V = qkv + (size_t)b*N*2304 + 1536 + h*HD;
    size_t cbase = (size_t)b*N*DD + h*HD;
    int row0 = blockIdx.y * 64;

    float acc[2][2][4];
    #pragma unroll
    for (int i = 0; i < 2; i++)
        #pragma unroll
        for (int j = 0; j < 2; j++)
            #pragma unroll
            for (int q = 0; q < 4; q++) acc[i][j][q] = 0.f;

    const float4 z4 = make_float4(0.f, 0.f, 0.f, 0.f);
    int pr = tid >> 2;
    int pc = (tid & 3) * 4;
    int vj = tid >> 4;
    int vd = (tid & 15) * 4;

    int ktiles = (N + 15) >> 4;
    for (int kt = 0; kt < ktiles; kt++) {
        int j0 = kt * 16;
        {
            int gi = row0 + pr;
            float pv[4], ph[4], pl[4];
            #pragma unroll
            for (int q = 0; q < 4; q++) {
                int jj = j0 + pc + q;
                pv[q] = (gi < N && jj < N) ? P[(size_t)gi*N + jj] : 0.f;
                uint32_t hh = f2tf(pv[q]);
                ph[q] = __uint_as_float(hh);
                pl[q] = pv[q] - ph[q];
            }
            *(float4*)&Ph[pr][pc] = make_float4(ph[0], ph[1], ph[2], ph[3]);
            *(float4*)&Pl[pr][pc] = make_float4(pl[0], pl[1], pl[2], pl[3]);
        }
        {
            int jj = j0 + vj;
            float4 vv = (jj < N) ? *(const float4*)(V + (size_t)jj*2304 + vd) : z4;
            float vvv[4] = {vv.x, vv.y, vv.z, vv.w};
            #pragma unroll
            for (int q = 0; q < 4; q++) {
                uint32_t hh = f2tf(vvv[q]);
                float hf = __uint_as_float(hh);
                Vh[vd + q][vj] = hf;
                Vl[vd + q][vj] = vvv[q] - hf;
            }
        }
        __syncthreads();
        #pragma unroll
        for (int ks = 0; ks < 2; ks++) {
            int k = ks*8 + tig;
            uint32_t bhf[2][2], blf[2][2];
            #pragma unroll
            for (int nt = 0; nt < 2; nt++) {
                int n = wn*16 + nt*8 + g;
                bhf[nt][0] = __float_as_uint(Vh[n][k]);
                bhf[nt][1] = __float_as_uint(Vh[n][k+4]);
                blf[nt][0] = __float_as_uint(Vl[n][k]);
                blf[nt][1] = __float_as_uint(Vl[n][k+4]);
            }
            #pragma unroll
            for (int mt = 0; mt < 2; mt++) {
                int r = wm*32 + mt*16 + g;
                uint32_t ah[4], al[4];
                ah[0] = __float_as_uint(Ph[r][k]);
                ah[1] = __float_as_uint(Ph[r+8][k]);
                ah[2] = __float_as_uint(Ph[r][k+4]);
                ah[3] = __float_as_uint(Ph[r+8][k+4]);
                al[0] = __float_as_uint(Pl[r][k]);
                al[1] = __float_as_uint(Pl[r+8][k]);
                al[2] = __float_as_uint(Pl[r][k+4]);
                al[3] = __float_as_uint(Pl[r+8][k+4]);
                #pragma unroll
                for (int nt = 0; nt < 2; nt++) {
                    mma_tf32(acc[mt][nt], al, bhf[nt]);
                    mma_tf32(acc[mt][nt], ah, blf[nt]);
                    mma_tf32(acc[mt][nt], ah, bhf[nt]);
                }
            }
        }
        __syncthreads();
    }

    #pragma unroll
    for (int mt = 0; mt < 2; mt++) {
        #pragma unroll
        for (int nt = 0; nt < 2; nt++) {
            int gc0 = wn*16 + nt*8 + 2*tig;
            #pragma unroll
            for (int half = 0; half < 2; half++) {
                int gr = row0 + wm*32 + mt*16 + g + half*8;
                if (gr >= N) continue;
                uint32_t hw, lw2;
                split2_bf16(acc[mt][nt][half*2], acc[mt][nt][half*2 + 1], hw, lw2);
                size_t off = cbase + (size_t)gr*DD + gc0;
                *(uint32_t*)(oh + off) = hw;
                *(uint32_t*)(ol + off) = lw2;
            }
        }
    }
}

// ---------------- SIMT GEMM (tiny shapes: N=1 predictor head, class head) -------
__global__ void gemm_kernel(const float* __restrict__ A, const float* __restrict__ W,
                            const float* __restrict__ bias, const float* __restrict__ resid,
                            float* __restrict__ C, int M, int N, int K, int act)
{
    __shared__ float As[16][65];
    __shared__ float Ws[16][65];
    int tx = threadIdx.x, ty = threadIdx.y;
    int tid = ty*16 + tx;
    int row0 = blockIdx.y*64, col0 = blockIdx.x*64;
    float acc[4][4] = {};
    for (int k0 = 0; k0 < K; k0 += 16) {
        #pragma unroll
        for (int i = 0; i < 4; i++) {
            int idx = tid + i*256;
            int r = idx >> 4;
            int c = idx & 15;
            int gr = row0 + r;
            As[c][r] = (gr < M) ? A[(size_t)gr*K + k0 + c] : 0.f;
            int wr = col0 + r;
            Ws[c][r] = (wr < N) ? W[(size_t)wr*K + k0 + c] : 0.f;
        }
        __syncthreads();
        #pragma unroll
        for (int kk = 0; kk < 16; kk++) {
            float a[4], bb[4];
            #pragma unroll
            for (int i = 0; i < 4; i++) a[i] = As[kk][ty*4+i];
            #pragma unroll
            for (int j = 0; j < 4; j++) bb[j] = Ws[kk][tx*4+j];
            #pragma unroll
            for (int i = 0; i < 4; i++)
                #pragma unroll
                for (int j = 0; j < 4; j++)
                    acc[i][j] = fmaf(a[i], bb[j], acc[i][j]);
        }
        __syncthreads();
    }
    #pragma unroll
    for (int i = 0; i < 4; i++) {
        int gr = row0 + ty*4 + i;
        if (gr >= M) continue;
        #pragma unroll
        for (int j = 0; j < 4; j++) {
            int gc = col0 + tx*4 + j;
            if (gc >= N) continue;
            float v = acc[i][j] + bias[gc];
            if (act == 1) v = gelu_f(v);
            if (resid) v += resid[(size_t)gr*N + gc];
            C[(size_t)gr*N + gc] = v;
        }
    }
}

// ---------------- LayerNorm: out = fp32 (dstf) or bf16 pair (dsth/dstl) --------
__global__ void ln_kernel(const float* __restrict__ src, float* __restrict__ dstf,
                          bf16* __restrict__ dsth, bf16* __restrict__ dstl,
                          const float* __restrict__ gamma, const float* __restrict__ beta,
                          int n_src_tokens, int toks_out, int tok_off)
{
    int r = blockIdx.x;
    int b = r / toks_out;
    int n = r % toks_out + tok_off;
    const float* x = src + ((size_t)b*n_src_tokens + n)*DD;
    int tid = threadIdx.x;                 // 256
    float v[3];
    float s = 0.f, s2 = 0.f;
    #pragma unroll
    for (int i = 0; i < 3; i++) { v[i] = x[tid + i*256]; s += v[i]; s2 += v[i]*v[i]; }
    __shared__ float sh1[8], sh2[8];
    #pragma unroll
    for (int o = 16; o > 0; o >>= 1) {
        s  += __shfl_xor_sync(0xffffffffu, s,  o);
        s2 += __shfl_xor_sync(0xffffffffu, s2, o);
    }
    if ((tid & 31) == 0) { sh1[tid>>5] = s; sh2[tid>>5] = s2; }
    __syncthreads();
    float ts = 0.f, ts2 = 0.f;
    #pragma unroll
    for (int w = 0; w < 8; w++) { ts += sh1[w]; ts2 += sh2[w]; }
    float mean = ts * (1.f/768.f);
    float var  = ts2 * (1.f/768.f) - mean*mean;
    float rstd = rsqrtf(var + 1e-6f);
    size_t ob = (size_t)r*DD;
    #pragma unroll
    for (int i = 0; i < 3; i++) {
        int c = tid + i*256;
        float y = (v[i] - mean) * rstd * gamma[c] + beta[c];
        if (dstf) dstf[ob + c] = y;
        else      split1(y, dsth[ob + c], dstl[ob + c]);
    }
}

// ---------------- predictor helpers ----------------
__global__ void globmean_kernel(const float* __restrict__ hidden, float* __restrict__ glob, int L)
{
    int b = blockIdx.x;
    int c = threadIdx.x;                   // 384
    float s = 0.f;
    for (int l = 0; l < L; l++) s += hidden[((size_t)b*L + l)*DD + 384 + c];
    glob[b*384 + c] = s / (float)L;
}

// combine -> bf16 pair
__global__ void combine_kernel(const float* __restrict__ hidden, const float* __restrict__ glob,
                               bf16* __restrict__ h2h, bf16* __restrict__ h2l, int L)
{
    int i = blockIdx.x * blockDim.x + threadIdx.x;
    int total = BB*L*DD;
    if (i >= total) return;
    int c = i % DD;
    int r = i / DD;
    int b = r / L;
    float v = (c < 384) ? hidden[i] : glob[b*384 + (c - 384)];
    split1(v, h2h[i], h2l[i]);
}

// exact jax top_k order via rank counting (score desc, index asc tie-break).
__global__ void topk_kernel(const float* __restrict__ score, int* __restrict__ idx, int L, int k)
{
    int b = blockIdx.x;
    __shared__ float s[LMAX];
    int t = threadIdx.x;                   // 256
    for (int j = t; j < L; j += blockDim.x) s[j] = score[b*L + j];
    __syncthreads();
    if (t < L) {
        float my = s[t];
        int rank = 0;
        for (int j = 0; j < L; j++) {
            float v = s[j];
            rank += (v > my) || (v == my && j < t);
        }
        if (rank < k) idx[b*LMAX + rank] = t;
    }
}

__global__ void gather_kernel(const float* __restrict__ tin, const int* __restrict__ idx,
                              float* __restrict__ tout, int Nin, int Nout)
{
    int i = blockIdx.x * blockDim.x + threadIdx.x;
    int total = BB*Nout*DD;
    if (i >= total) return;
    int c = i % DD;
    int r = i / DD;
    int b = r / Nout;
    int j = r % Nout;
    int n = (j == 0) ? 0 : (1 + idx[b*LMAX + (j - 1)]);
    tout[i] = tin[((size_t)b*Nin + n)*DD + c];
}

// ---------------- host orchestration ----------------
static inline void launch_gemm2(const bf16* Ah, const bf16* Al,
                                const bf16* Wh, const bf16* Wl,
                                const float* bias, const float* resid,
                                float* Cf, bf16* Ch, bf16* Cl,
                                int M, int N, int K, int act)
{
    dim3 grid((N + 127) / 128, (M + 127) / 128);
    gemm_tc2_kernel<<<grid, 256>>>(Ah, Al, Wh, Wl, bias, resid, Cf, Ch, Cl, M, N, K, act);
}

static inline void launch_gemm(const float* A, const float* W, const float* bias,
                               const float* resid, float* C, int M, int N, int K, int act)
{
    dim3 grid((N + 63) / 64, (M + 63) / 64);
    dim3 block(16, 16);
    gemm_kernel<<<grid, block>>>(A, W, bias, resid, C, M, N, K, act);
}

static inline void launch_split(const float* in, bf16* hi, bf16* lo, int n)
{
    int n4 = n / 4;
    split_kernel<<<(n4 + 255) / 256, 256>>>(in, hi, lo, n4);
}

extern "C" void kernel_launch(void* const* d_in, const int* in_sizes, int n_in,
                              void* d_out, int out_size)
{
    const float* x       = (const float*)d_in[0];
    const float* patch_w = (const float*)d_in[1];
    const float* patch_b = (const float*)d_in[2];
    const float* cls_tok = (const float*)d_in[3];
    const float* pos     = (const float*)d_in[4];
    const float* ln1_g   = (const float*)d_in[5];
    const float* ln1_b   = (const float*)d_in[6];
    const float* qkv_w   = (const float*)d_in[7];
    const float* qkv_b   = (const float*)d_in[8];
    const float* proj_w  = (const float*)d_in[9];
    const float* proj_b  = (const float*)d_in[10];
    const float* ln2_g   = (const float*)d_in[11];
    const float* ln2_b   = (const float*)d_in[12];
    const float* fc1_w   = (const float*)d_in[13];
    const float* fc1_b   = (const float*)d_in[14];
    const float* fc2_w   = (const float*)d_in[15];
    const float* fc2_b   = (const float*)d_in[16];
    const float* pln_g   = (const float*)d_in[17];
    const float* pln_b   = (const float*)d_in[18];
    const float* pin_w   = (const float*)d_in[19];
    const float* pin_b   = (const float*)d_in[20];
    const float* pw1     = (const float*)d_in[21];
    const float* pb1     = (const float*)d_in[22];
    const float* pw2     = (const float*)d_in[23];
    const float* pb2     = (const float*)d_in[24];
    const float* pw3     = (const float*)d_in[25];
    const float* pb3     = (const float*)d_in[26];
    const float* norm_g  = (const float*)d_in[27];
    const float* norm_b  = (const float*)d_in[28];
    const float* head_w  = (const float*)d_in[29];
    const float* head_b  = (const float*)d_in[30];
    (void)in_sizes; (void)n_in; (void)out_size;

    void* p;
    cudaGetSymbolAddress(&p, g_t0);    float* t0    = (float*)p;
    cudaGetSymbolAddress(&p, g_t1);    float* t1    = (float*)p;
    cudaGetSymbolAddress(&p, g_qkv);   float* qkvb  = (float*)p;
    cudaGetSymbolAddress(&p, g_pa);    float* pa    = (float*)p;
    cudaGetSymbolAddress(&p, g_pb);    float* pbuf  = (float*)p;
    cudaGetSymbolAddress(&p, g_glob);  float* glob  = (float*)p;
    cudaGetSymbolAddress(&p, g_score); float* score = (float*)p;
    cudaGetSymbolAddress(&p, g_idx);   int*   gidx  = (int*)p;
    cudaGetSymbolAddress(&p, g_cls);   float* clsb  = (float*)p;
    cudaGetSymbolAddress(&p, g_att);   float* attb  = (float*)p;

    cudaGetSymbolAddress(&p, g_lnh);   bf16* lnh  = (bf16*)p;
    cudaGetSymbolAddress(&p, g_lnl);   bf16* lnl  = (bf16*)p;
    cudaGetSymbolAddress(&p, g_aoh);   bf16* aoh  = (bf16*)p;
    cudaGetSymbolAddress(&p, g_aol);   bf16* aol  = (bf16*)p;
    cudaGetSymbolAddress(&p, g_mlph);  bf16* mlph = (bf16*)p;
    cudaGetSymbolAddress(&p, g_mlpl);  bf16* mlpl = (bf16*)p;
    cudaGetSymbolAddress(&p, g_imh);   bf16* imh  = (bf16*)p;
    cudaGetSymbolAddress(&p, g_iml);   bf16* iml  = (bf16*)p;
    cudaGetSymbolAddress(&p, g_ppbh);  bf16* ppbh = (bf16*)p;
    cudaGetSymbolAddress(&p, g_ppbl);  bf16* ppbl = (bf16*)p;

    cudaGetSymbolAddress(&p, g_qkvwh);  bf16* qkvwh  = (bf16*)p;
    cudaGetSymbolAddress(&p, g_qkvwl);  bf16* qkvwl  = (bf16*)p;
    cudaGetSymbolAddress(&p, g_projwh); bf16* projwh = (bf16*)p;
    cudaGetSymbolAddress(&p, g_projwl); bf16* projwl = (bf16*)p;
    cudaGetSymbolAddress(&p, g_fc1wh);  bf16* fc1wh  = (bf16*)p;
    cudaGetSymbolAddress(&p, g_fc1wl);  bf16* fc1wl  = (bf16*)p;
    cudaGetSymbolAddress(&p, g_fc2wh);  bf16* fc2wh  = (bf16*)p;
    cudaGetSymbolAddress(&p, g_fc2wl);  bf16* fc2wl  = (bf16*)p;
    cudaGetSymbolAddress(&p, g_patchwh); bf16* patchwh = (bf16*)p;
    cudaGetSymbolAddress(&p, g_patchwl); bf16* patchwl = (bf16*)p;
    cudaGetSymbolAddress(&p, g_pinwh);  bf16* pinwh  = (bf16*)p;
    cudaGetSymbolAddress(&p, g_pinwl);  bf16* pinwl  = (bf16*)p;
    cudaGetSymbolAddress(&p, g_pw1h);   bf16* pw1h   = (bf16*)p;
    cudaGetSymbolAddress(&p, g_pw1l);   bf16* pw1l   = (bf16*)p;
    cudaGetSymbolAddress(&p, g_pw2h);   bf16* pw2h   = (bf16*)p;
    cudaGetSymbolAddress(&p, g_pw2l);   bf16* pw2l   = (bf16*)p;

    // weight splits (every replay; ~0.12 ms bandwidth-bound)
    launch_split(qkv_w,   qkvwh,  qkvwl,  SZ_QKVW);
    launch_split(proj_w,  projwh, projwl, SZ_PROJW);
    launch_split(fc1_w,   fc1wh,  fc1wl,  SZ_FC1W);
    launch_split(fc2_w,   fc2wh,  fc2wl,  SZ_FC2W);
    launch_split(patch_w, patchwh, patchwl, SZ_PATCHW);
    launch_split(pin_w,   pinwh,  pinwl,  SZ_PINW);
    launch_split(pw1,     pw1h,   pw1l,   SZ_PW1);
    launch_split(pw2,     pw2h,   pw2l,   SZ_PW2);

    // patch embedding
    { int total = BB*LMAX*DD; im2col_kernel<<<(total + 255)/256, 256>>>(x, imh, iml); }
    launch_gemm2(imh, iml, patchwh, patchwl, patch_b, nullptr, pbuf, nullptr, nullptr,
                 BB*LMAX, DD, DD, 0);
    { int total = BB*NMAX*DD; assemble_kernel<<<(total + 255)/256, 256>>>(pbuf, cls_tok, pos, t0); }

    float* ta = t0;
    float* tb = t1;
    int N = NMAX;
    const int kkeep[3] = {138, 97, 68};

    for (int i = 0; i < 12; i++) {
        int s = (i == 3) ? 0 : (i == 6) ? 1 : (i == 9) ? 2 : -1;
        if (s >= 0) {
            int L = N - 1;
            int M = BB * L;
            ln_kernel<<<M, 256>>>(ta, nullptr, imh, iml, pln_g + s*DD, pln_b + s*DD, N, L, 1);
            launch_gemm2(imh, iml, pinwh + (size_t)s*DD*DD, pinwl + (size_t)s*DD*DD,
                         pin_b + s*DD, nullptr, pbuf, nullptr, nullptr, M, DD, DD, 1);
            globmean_kernel<<<BB, 384>>>(pbuf, glob, L);
            { int total = M*DD; combine_kernel<<<(total + 255)/256, 256>>>(pbuf, glob, imh, iml, L); }
            launch_gemm2(imh, iml, pw1h + (size_t)s*384*DD, pw1l + (size_t)s*384*DD,
                         pb1 + s*384, nullptr, nullptr, ppbh, ppbl, M, 384, DD, 1);
            launch_gemm2(ppbh, ppbl, pw2h + (size_t)s*192*384, pw2l + (size_t)s*192*384,
                         pb2 + s*192, nullptr, pa, nullptr, nullptr, M, 192, 384, 1);
            launch_gemm(pa, pw3 + (size_t)s*192, pb3 + s, nullptr, score, M, 1, 192, 0);
            topk_kernel<<<BB, 256>>>(score, gidx, L, kkeep[s]);
            int Nn = kkeep[s] + 1;
            { int total = BB*Nn*DD; gather_kernel<<<(total + 255)/256, 256>>>(ta, gidx, tb, N, Nn); }
            float* tmp = ta; ta = tb; tb = tmp;
            N = Nn;
        }
        int M = BB * N;
        int ntile = (N + 63) / 64;
        ln_kernel<<<M, 256>>>(ta, nullptr, lnh, lnl, ln1_g + i*DD, ln1_b + i*DD, N, N, 0);
        launch_gemm2(lnh, lnl, qkvwh + (size_t)i*2304*DD, qkvwl + (size_t)i*2304*DD,
                     qkv_b + i*2304, nullptr, qkvb, nullptr, nullptr, M, 2304, DD, 0);
        {
            dim3 gqk(ntile, ntile, BB*NHD);
            attn_qk_kernel<<<gqk, 256>>>(qkvb, attb, N);
            int rows = BB*NHD*N;
            attn_softmax_kernel<<<(rows + 3)/4, 128>>>(attb, N, rows);
            dim3 gpv(1, ntile, BB*NHD);
            attn_pv_kernel<<<gpv, 256>>>(attb, qkvb, aoh, aol, N);
        }
        launch_gemm2(aoh, aol, projwh + (size_t)i*DD*DD, projwl + (size_t)i*DD*DD,
                     proj_b + i*DD, ta, tb, nullptr, nullptr, M, DD, DD, 0);
        ln_kernel<<<M, 256>>>(tb, nullptr, lnh, lnl, ln2_g + i*DD, ln2_b + i*DD, N, N, 0);
        launch_gemm2(lnh, lnl, fc1wh + (size_t)i*3072*DD, fc1wl + (size_t)i*3072*DD,
                     fc1_b + i*3072, nullptr, nullptr, mlph, mlpl, M, 3072, DD, 1);
        launch_gemm2(mlph, mlpl, fc2wh + (size_t)i*DD*3072, fc2wl + (size_t)i*DD*3072,
                     fc2_b + i*DD, tb, ta, nullptr, nullptr, M, DD, 3072, 0);
    }

    // final LN on cls token + classification head
    ln_kernel<<<BB, 256>>>(ta, clsb, nullptr, nullptr, norm_g, norm_b, N, 1, 0);
    launch_gemm(clsb, head_w, head_b, nullptr, (float*)d_out, BB, 1000, DD, 0);
}

// round 11
// speedup vs baseline: 1.2181x; 1.2181x over previous
#include <cuda_runtime.h>
#include <cuda_bf16.h>
#include <math.h>
#include <stdint.h>

#define BB   32
#define DD   768
#define NHD  12
#define HD   64
#define NMAX 197
#define LMAX 196
#define ATTN_SCALE 0.125f

typedef __nv_bfloat16 bf16;

// ---------------- weight pair sizes ----------------
#define SZ_QKVW  (12*2304*768)
#define SZ_PROJW (12*768*768)
#define SZ_FC1W  (12*3072*768)
#define SZ_FC2W  (12*3072*768)
#define SZ_PATCHW (768*768)
#define SZ_PINW  (3*768*768)
#define SZ_PW1   (3*384*768)
#define SZ_PW2   (3*192*384)

// ---------------- scratch (device globals; no allocation allowed) ----------------
__device__ float g_t0[BB*NMAX*DD];
__device__ float g_t1[BB*NMAX*DD];
__device__ float g_qkv[BB*NMAX*2304];
__device__ float g_pa[BB*LMAX*DD];
__device__ float g_pb[BB*LMAX*DD];
__device__ float g_glob[BB*384];
__device__ float g_score[BB*LMAX];
__device__ int   g_idx[BB*LMAX];
__device__ float g_cls[BB*DD];
__device__ float g_att[(size_t)BB*NHD*NMAX*NMAX];

// bf16 hi/lo activation pairs
__device__ bf16 g_lnh[BB*NMAX*DD],  g_lnl[BB*NMAX*DD];
__device__ bf16 g_aoh[BB*NMAX*DD],  g_aol[BB*NMAX*DD];
__device__ bf16 g_mlph[BB*NMAX*3072], g_mlpl[BB*NMAX*3072];
__device__ bf16 g_imh[BB*LMAX*DD],  g_iml[BB*LMAX*DD];
__device__ bf16 g_ppbh[BB*LMAX*384], g_ppbl[BB*LMAX*384];

// bf16 hi/lo weight pairs
__device__ bf16 g_qkvwh[SZ_QKVW],  g_qkvwl[SZ_QKVW];
__device__ bf16 g_projwh[SZ_PROJW], g_projwl[SZ_PROJW];
__device__ bf16 g_fc1wh[SZ_FC1W],  g_fc1wl[SZ_FC1W];
__device__ bf16 g_fc2wh[SZ_FC2W],  g_fc2wl[SZ_FC2W];
__device__ bf16 g_patchwh[SZ_PATCHW], g_patchwl[SZ_PATCHW];
__device__ bf16 g_pinwh[SZ_PINW],  g_pinwl[SZ_PINW];
__device__ bf16 g_pw1h[SZ_PW1],    g_pw1l[SZ_PW1];
__device__ bf16 g_pw2h[SZ_PW2],    g_pw2l[SZ_PW2];

__device__ __forceinline__ float gelu_f(float x) {
    return 0.5f * x * (1.f + erff(x * 0.70710678118654752440f));
}

__device__ __forceinline__ void split1(float v, bf16& h, bf16& l) {
    h = __float2bfloat16(v);
    l = __float2bfloat16(v - __bfloat162float(h));
}

// split two floats into packed bf16 hi pair + lo pair
__device__ __forceinline__ void split2_bf16(float v0, float v1, uint32_t& hi, uint32_t& lo) {
    bf16 h0 = __float2bfloat16(v0);
    bf16 h1 = __float2bfloat16(v1);
    float r0 = v0 - __bfloat162float(h0);
    float r1 = v1 - __bfloat162float(h1);
    bf16 l0 = __float2bfloat16(r0);
    bf16 l1 = __float2bfloat16(r1);
    hi = (uint32_t)__bfloat16_as_ushort(h0) | ((uint32_t)__bfloat16_as_ushort(h1) << 16);
    lo = (uint32_t)__bfloat16_as_ushort(l0) | ((uint32_t)__bfloat16_as_ushort(l1) << 16);
}

// ---------------- weight split: fp32 -> bf16 hi/lo pairs ----------------
__global__ void split_kernel(const float* __restrict__ in, bf16* __restrict__ hi,
                             bf16* __restrict__ lo, int n4)
{
    int i = blockIdx.x * blockDim.x + threadIdx.x;
    if (i >= n4) return;
    float4 v = ((const float4*)in)[i];
    uint32_t h0, l0, h1, l1;
    split2_bf16(v.x, v.y, h0, l0);
    split2_bf16(v.z, v.w, h1, l1);
    ((uint32_t*)hi)[i*2]   = h0;
    ((uint32_t*)hi)[i*2+1] = h1;
    ((uint32_t*)lo)[i*2]   = l0;
    ((uint32_t*)lo)[i*2+1] = l1;
}

// ---------------- im2col for patch embedding (writes bf16 pair) ----------------
__global__ void im2col_kernel(const float* __restrict__ x, bf16* __restrict__ ph,
                              bf16* __restrict__ pl) {
    int i = blockIdx.x * blockDim.x + threadIdx.x;
    const int total = BB*LMAX*DD;
    if (i >= total) return;
    int c = i % DD;
    int r = i / DD;
    int b = r / LMAX;
    int l = r % LMAX;
    int gy = l / 14, gx = l % 14;
    int ch = c / 256, rem = c % 256, py = rem / 16, px = rem % 16;
    float v = x[(((size_t)b*3 + ch)*224 + gy*16 + py)*224 + gx*16 + px];
    split1(v, ph[i], pl[i]);
}

// assemble t = [cls | patches] + pos
__global__ void assemble_kernel(const float* __restrict__ pe, const float* __restrict__ cls,
                                const float* __restrict__ pos, float* __restrict__ t) {
    int i = blockIdx.x * blockDim.x + threadIdx.x;
    const int total = BB*NMAX*DD;
    if (i >= total) return;
    int d = i % DD;
    int n = (i / DD) % NMAX;
    int b = i / (DD*NMAX);
    float v = (n == 0) ? cls[d] : pe[((size_t)b*LMAX + (n-1))*DD + d];
    t[i] = v + pos[n*DD + d];
}

// =====================================================================
// mma helpers
// =====================================================================
#define SK 20   // smem row stride (words): conflict-free frag loads

__device__ __forceinline__ uint32_t f2tf(float f) {
    uint32_t u;
    asm("cvt.rna.tf32.f32 %0, %1;" : "=r"(u) : "f"(f));
    return u;
}

__device__ __forceinline__ void mma_tf32(float d[4], const uint32_t a[4], const uint32_t b[2]) {
    asm volatile(
        "mma.sync.aligned.m16n8k8.row.col.f32.tf32.tf32.f32 "
        "{%0,%1,%2,%3}, {%4,%5,%6,%7}, {%8,%9}, {%0,%1,%2,%3};\n"
        : "+f"(d[0]), "+f"(d[1]), "+f"(d[2]), "+f"(d[3])
        : "r"(a[0]), "r"(a[1]), "r"(a[2]), "r"(a[3]), "r"(b[0]), "r"(b[1]));
}

__device__ __forceinline__ void mma_bf16(float d[4], const uint32_t a[4], const uint32_t b[2]) {
    asm volatile(
        "mma.sync.aligned.m16n8k16.row.col.f32.bf16.bf16.f32 "
        "{%0,%1,%2,%3}, {%4,%5,%6,%7}, {%8,%9}, {%0,%1,%2,%3};\n"
        : "+f"(d[0]), "+f"(d[1]), "+f"(d[2]), "+f"(d[3])
        : "r"(a[0]), "r"(a[1]), "r"(a[2]), "r"(a[3]), "r"(b[0]), "r"(b[1]));
}

// =====================================================================
// Tensor-core GEMM v3: C = act(A[M,K] @ W[N,K]^T + bias) (+resid)
// A and W are pre-split bf16 hi/lo pairs; pure-copy loader, BK=32 so
// each row contributes 64B contiguous -> 4 lanes x 16B coalesced loads
// (same granularity as the fast R9 fp32 loader, at half the bytes).
// 128x128x32 CTA tile, 256 threads, warp grid 2x4, warp tile 64x32.
// Output: fp32 (Cf) or bf16 pair (Ch/Cl).
// =====================================================================
__global__ __launch_bounds__(256)
void gemm_tc2_kernel(const bf16* __restrict__ Ahg, const bf16* __restrict__ Alg,
                     const bf16* __restrict__ Whg, const bf16* __restrict__ Wlg,
                     const float* __restrict__ bias, const float* __restrict__ resid,
                     float* __restrict__ Cf, bf16* __restrict__ Ch, bf16* __restrict__ Cl,
                     int M, int N, int K, int act)
{
    // 32 bf16 per row = 16 words (+4 pad)
    __shared__ __align__(16) uint32_t Ah[128][SK];
    __shared__ __align__(16) uint32_t Al[128][SK];
    __shared__ __align__(16) uint32_t Bh[128][SK];
    __shared__ __align__(16) uint32_t Bl[128][SK];

    int tid = threadIdx.x;
    int lane = tid & 31, w = tid >> 5;
    int wm = w >> 2, wn = w & 3;          // warp grid 2x4
    int g = lane >> 2, tig = lane & 3;    // mma quad coords
    int row0 = blockIdx.y * 128, col0 = blockIdx.x * 128;

    float acc[4][4][4];
    #pragma unroll
    for (int i = 0; i < 4; i++)
        #pragma unroll
        for (int j = 0; j < 4; j++)
            #pragma unroll
            for (int q = 0; q < 4; q++) acc[i][j][q] = 0.f;

    int lr = tid >> 2;            // tile row 0..63 (pass adds 64)
    int le = (tid & 3) * 8;       // element col offset: 0,8,16,24
    int lw = (tid & 3) * 4;       // smem word col: 0,4,8,12

    const uint4 z4 = make_uint4(0u, 0u, 0u, 0u);
    uint4 pAh[2], pAl[2], pBh[2], pBl[2];

    // initial prefetch (k0 = 0)
    #pragma unroll
    for (int i = 0; i < 2; i++) {
        int gr = row0 + lr + i*64;
        pAh[i] = (gr < M) ? *(const uint4*)(Ahg + (size_t)gr*K + le) : z4;
        pAl[i] = (gr < M) ? *(const uint4*)(Alg + (size_t)gr*K + le) : z4;
        int wr = col0 + lr + i*64;
        pBh[i] = (wr < N) ? *(const uint4*)(Whg + (size_t)wr*K + le) : z4;
        pBl[i] = (wr < N) ? *(const uint4*)(Wlg + (size_t)wr*K + le) : z4;
    }

    int ktiles = K >> 5;
    for (int kt = 0; kt < ktiles; kt++) {
        #pragma unroll
        for (int i = 0; i < 2; i++) {
            int r = lr + i*64;
            *(uint4*)&Ah[r][lw] = pAh[i];
            *(uint4*)&Al[r][lw] = pAl[i];
            *(uint4*)&Bh[r][lw] = pBh[i];
            *(uint4*)&Bl[r][lw] = pBl[i];
        }
        __syncthreads();

        // prefetch next tile (overlaps with mma below)
        if (kt + 1 < ktiles) {
            int k0 = (kt + 1) << 5;
            #pragma unroll
            for (int i = 0; i < 2; i++) {
                int gr = row0 + lr + i*64;
                pAh[i] = (gr < M) ? *(const uint4*)(Ahg + (size_t)gr*K + k0 + le) : z4;
                pAl[i] = (gr < M) ? *(const uint4*)(Alg + (size_t)gr*K + k0 + le) : z4;
                int wr = col0 + lr + i*64;
                pBh[i] = (wr < N) ? *(const uint4*)(Whg + (size_t)wr*K + k0 + le) : z4;
                pBl[i] = (wr < N) ? *(const uint4*)(Wlg + (size_t)wr*K + k0 + le) : z4;
            }
        }

        // compute: 2 x m16n8k16 over the 32-wide k tile
        #pragma unroll
        for (int ks = 0; ks < 2; ks++) {
            int off = ks * 8;
            uint32_t bhf[4][2], blf[4][2];
            #pragma unroll
            for (int nt = 0; nt < 4; nt++) {
                int n = wn*32 + nt*8 + g;
                bhf[nt][0] = Bh[n][tig+off];
                bhf[nt][1] = Bh[n][tig+off+4];
                blf[nt][0] = Bl[n][tig+off];
                blf[nt][1] = Bl[n][tig+off+4];
            }
            #pragma unroll
            for (int mt = 0; mt < 4; mt++) {
                int r = wm*64 + mt*16 + g;
                uint32_t ah[4], al[4];
                ah[0] = Ah[r][tig+off];
                ah[1] = Ah[r+8][tig+off];
                ah[2] = Ah[r][tig+off+4];
                ah[3] = Ah[r+8][tig+off+4];
                al[0] = Al[r][tig+off];
                al[1] = Al[r+8][tig+off];
                al[2] = Al[r][tig+off+4];
                al[3] = Al[r+8][tig+off+4];
                #pragma unroll
                for (int nt = 0; nt < 4; nt++) {
                    mma_bf16(acc[mt][nt], al, bhf[nt]);   // lo*hi
                    mma_bf16(acc[mt][nt], ah, blf[nt]);   // hi*lo
                    mma_bf16(acc[mt][nt], ah, bhf[nt]);   // hi*hi
                }
            }
        }
        __syncthreads();
    }

    // epilogue
    #pragma unroll
    for (int mt = 0; mt < 4; mt++) {
        #pragma unroll
        for (int nt = 0; nt < 4; nt++) {
            int gc0 = col0 + wn*32 + nt*8 + 2*tig;
            #pragma unroll
            for (int half = 0; half < 2; half++) {
                int gr = row0 + wm*64 + mt*16 + g + half*8;
                if (gr >= M) continue;
                if (Cf) {
                    #pragma unroll
                    for (int j = 0; j < 2; j++) {
                        int gc = gc0 + j;
                        if (gc >= N) continue;
                        float v = acc[mt][nt][half*2 + j] + bias[gc];
                        if (act == 1) v = gelu_f(v);
                        if (resid) v += resid[(size_t)gr*N + gc];
                        Cf[(size_t)gr*N + gc] = v;
                    }
                } else {
                    if (gc0 + 1 >= N) continue;
                    float v0 = acc[mt][nt][half*2 + 0] + bias[gc0];
                    float v1 = acc[mt][nt][half*2 + 1] + bias[gc0+1];
                    if (act == 1) { v0 = gelu_f(v0); v1 = gelu_f(v1); }
                    uint32_t hw, lw2;
                    split2_bf16(v0, v1, hw, lw2);
                    *(uint32_t*)(Ch + (size_t)gr*N + gc0) = hw;
                    *(uint32_t*)(Cl + (size_t)gr*N + gc0) = lw2;
                }
            }
        }
    }
}

// =====================================================================
// Batched attention, stage 1: scores = Q @ K^T per (b,h). 3xTF32.
// =====================================================================
__global__ __launch_bounds__(256)
void attn_qk_kernel(const float* __restrict__ qkv, float* __restrict__ att, int N)
{
    __shared__ __align__(16) float Ah[64][SK];
    __shared__ __align__(16) float Al[64][SK];
    __shared__ __align__(16) float Bh[64][SK];
    __shared__ __align__(16) float Bl[64][SK];

    int tid = threadIdx.x;
    int lane = tid & 31, w = tid >> 5;
    int wm = w >> 2, wn = w & 3;
    int g = lane >> 2, tig = lane & 3;
    int bh = blockIdx.z;
    int b = bh / NHD, h = bh % NHD;
    const float* Q  = qkv + (size_t)b*N*2304 + h*HD;
    const float* Kp = qkv + (size_t)b*N*2304 + 768 + h*HD;
    float* C = att + (size_t)bh*N*N;
    int row0 = blockIdx.y * 64, col0 = blockIdx.x * 64;

    float acc[2][2][4];
    #pragma unroll
    for (int i = 0; i < 2; i++)
        #pragma unroll
        for (int j = 0; j < 2; j++)
            #pragma unroll
            for (int q = 0; q < 4; q++) acc[i][j][q] = 0.f;

    int ldr = tid >> 2;
    int ldc = (tid & 3) * 4;
    const float4 z4 = make_float4(0.f, 0.f, 0.f, 0.f);

    #pragma unroll
    for (int kt = 0; kt < 4; kt++) {
        int k0 = kt * 16;
        {
            int gr = row0 + ldr;
            float4 va = (gr < N) ? *(const float4*)(Q + (size_t)gr*2304 + k0 + ldc) : z4;
            int wr = col0 + ldr;
            float4 vb = (wr < N) ? *(const float4*)(Kp + (size_t)wr*2304 + k0 + ldc) : z4;
            float av[4] = {va.x, va.y, va.z, va.w};
            float bv[4] = {vb.x, vb.y, vb.z, vb.w};
            float4 ah4, al4, bh4, bl4;
            float* ahp = &ah4.x; float* alp = &al4.x;
            float* bhp = &bh4.x; float* blp = &bl4.x;
            #pragma unroll
            for (int j = 0; j < 4; j++) {
                uint32_t hh = f2tf(av[j]);
                ahp[j] = __uint_as_float(hh);
                alp[j] = av[j] - ahp[j];
                uint32_t hb = f2tf(bv[j]);
                bhp[j] = __uint_as_float(hb);
                blp[j] = bv[j] - bhp[j];
            }
            *(float4*)&Ah[ldr][ldc] = ah4;
            *(float4*)&Al[ldr][ldc] = al4;
            *(float4*)&Bh[ldr][ldc] = bh4;
            *(float4*)&Bl[ldr][ldc] = bl4;
        }
        __syncthreads();
        #pragma unroll
        for (int ks = 0; ks < 2; ks++) {
            int k = ks*8 + tig;
            uint32_t bhf[2][2], blf[2][2];
            #pragma unroll
            for (int nt = 0; nt < 2; nt++) {
                int n = wn*16 + nt*8 + g;
                bhf[nt][0] = __float_as_uint(Bh[n][k]);
                bhf[nt][1] = __float_as_uint(Bh[n][k+4]);
                blf[nt][0] = __float_as_uint(Bl[n][k]);
                blf[nt][1] = __float_as_uint(Bl[n][k+4]);
            }
            #pragma unroll
            for (int mt = 0; mt < 2; mt++) {
                int r = wm*32 + mt*16 + g;
                uint32_t ah[4], al[4];
                ah[0] = __float_as_uint(Ah[r][k]);
                ah[1] = __float_as_uint(Ah[r+8][k]);
                ah[2] = __float_as_uint(Ah[r][k+4]);
                ah[3] = __float_as_uint(Ah[r+8][k+4]);
                al[0] = __float_as_uint(Al[r][k]);
                al[1] = __float_as_uint(Al[r+8][k]);
                al[2] = __float_as_uint(Al[r][k+4]);
                al[3] = __float_as_uint(Al[r+8][k+4]);
                #pragma unroll
                for (int nt = 0; nt < 2; nt++) {
                    mma_tf32(acc[mt][nt], al, bhf[nt]);
                    mma_tf32(acc[mt][nt], ah, blf[nt]);
                    mma_tf32(acc[mt][nt], ah, bhf[nt]);
                }
            }
        }
        __syncthreads();
    }

    #pragma unroll
    for (int mt = 0; mt < 2; mt++) {
        #pragma unroll
        for (int nt = 0; nt < 2; nt++) {
            int gc0 = col0 + wn*16 + nt*8 + 2*tig;
            #pragma unroll
            for (int half = 0; half < 2; half++) {
                int gr = row0 + wm*32 + mt*16 + g + half*8;
                if (gr >= N) continue;
                #pragma unroll
                for (int j = 0; j < 2; j++) {
                    int gc = gc0 + j;
                    if (gc < N) C[(size_t)gr*N + gc] = acc[mt][nt][half*2 + j];
                }
            }
        }
    }
}

// =====================================================================
// Batched attention, stage 2: in-place row softmax of scaled scores.
// =====================================================================
__global__ void attn_softmax_kernel(float* __restrict__ att, int N, int rows)
{
    int row = blockIdx.x * 4 + (threadIdx.x >> 5);
    if (row >= rows) return;
    int lane = threadIdx.x & 31;
    float* p = att + (size_t)row * N;
    float v[7];
    int cnt = 0;
    float m = -1e30f;
    for (int j = lane; j < N; j += 32) { float s = p[j]; v[cnt++] = s; m = fmaxf(m, s); }
    #pragma unroll
    for (int o = 16; o > 0; o >>= 1) m = fmaxf(m, __shfl_xor_sync(0xffffffffu, m, o));
    float sum = 0.f;
    #pragma unroll
    for (int q = 0; q < 7; q++) {
        if (q < cnt) { v[q] = expf((v[q] - m) * ATTN_SCALE); sum += v[q]; }
    }
    #pragma unroll
    for (int o = 16; o > 0; o >>= 1) sum += __shfl_xor_sync(0xffffffffu, sum, o);
    float inv = 1.f / sum;
    cnt = 0;
    for (int j = lane; j < N; j += 32) p[j] = v[cnt++] * inv;
}

// =====================================================================
// Batched attention, stage 3: O = P @ V per (b,h). Writes bf16 pair.
// =====================================================================
__global__ __launch_bounds__(256)
void attn_pv_kernel(const float* __restrict__ att, const float* __restrict__ qkv,
                    bf16* __restrict__ oh, bf16* __restrict__ ol, int N)
{
    __shared__ __align__(16) float Ph[64][SK];
    __shared__ __align__(16) float Pl[64][SK];
    __shared__ __align__(16) float Vh[64][SK];   // [d][j]
    __shared__ __align__(16) float Vl[64][SK];

    int tid = threadIdx.x;
    int lane = tid & 31, w = tid >> 5;
    int wm = w >> 2, wn = w & 3;
    int g = lane >> 2, tig = lane & 3;
    int bh = blockIdx.z;
    int b = bh / NHD, h = bh % NHD;
    const float* P = att + (size_t)bh*N*N;
    const float* V = qkv + (size_t)b*N*2304 + 1536 + h*HD;
    size_t cbase = (size_t)b*N*DD + h*HD;
    int row0 = blockIdx.y * 64;

    float acc[2][2][4];
    #pragma unroll
    for (int i = 0; i < 2; i++)
        #pragma unroll
        for (int j = 0; j < 2; j++)
            #pragma unroll
            for (int q = 0; q < 4; q++) acc[i][j][q] = 0.f;

    const float4 z4 = make_float4(0.f, 0.f, 0.f, 0.f);
    int pr = tid >> 2;
    int pc = (tid & 3) * 4;
    int vj = tid >> 4;
    int vd = (tid & 15) * 4;

    int ktiles = (N + 15) >> 4;
    for (int kt = 0; kt < ktiles; kt++) {
        int j0 = kt * 16;
        {
            int gi = row0 + pr;
            float pv[4], ph[4], pl[4];
            #pragma unroll
            for (int q = 0; q < 4; q++) {
                int jj = j0 + pc + q;
                pv[q] = (gi < N && jj < N) ? P[(size_t)gi*N + jj] : 0.f;
                uint32_t hh = f2tf(pv[q]);
                ph[q] = __uint_as_float(hh);
                pl[q] = pv[q] - ph[q];
            }
            *(float4*)&Ph[pr][pc] = make_float4(ph[0], ph[1], ph[2], ph[3]);
            *(float4*)&Pl[pr][pc] = make_float4(pl[0], pl[1], pl[2], pl[3]);
        }
        {
            int jj = j0 + vj;
            float4 vv = (jj < N) ? *(const float4*)(V + (size_t)jj*2304 + vd) : z4;
            float vvv[4] = {vv.x, vv.y, vv.z, vv.w};
            #pragma unroll
            for (int q = 0; q < 4; q++) {
                uint32_t hh = f2tf(vvv[q]);
                float hf = __uint_as_float(hh);
                Vh[vd + q][vj] = hf;
                Vl[vd + q][vj] = vvv[q] - hf;
            }
        }
        __syncthreads();
        #pragma unroll
        for (int ks = 0; ks < 2; ks++) {
            int k = ks*8 + tig;
            uint32_t bhf[2][2], blf[2][2];
            #pragma unroll
            for (int nt = 0; nt < 2; nt++) {
                int n = wn*16 + nt*8 + g;
                bhf[nt][0] = __float_as_uint(Vh[n][k]);
                bhf[nt][1] = __float_as_uint(Vh[n][k+4]);
                blf[nt][0] = __float_as_uint(Vl[n][k]);
                blf[nt][1] = __float_as_uint(Vl[n][k+4]);
            }
            #pragma unroll
            for (int mt = 0; mt < 2; mt++) {
                int r = wm*32 + mt*16 + g;
                uint32_t ah[4], al[4];
                ah[0] = __float_as_uint(Ph[r][k]);
                ah[1] = __float_as_uint(Ph[r+8][k]);
                ah[2] = __float_as_uint(Ph[r][k+4]);
                ah[3] = __float_as_uint(Ph[r+8][k+4]);
                al[0] = __float_as_uint(Pl[r][k]);
                al[1] = __float_as_uint(Pl[r+8][k]);
                al[2] = __float_as_uint(Pl[r][k+4]);
                al[3] = __float_as_uint(Pl[r+8][k+4]);
                #pragma unroll
                for (int nt = 0; nt < 2; nt++) {
                    mma_tf32(acc[mt][nt], al, bhf[nt]);
                    mma_tf32(acc[mt][nt], ah, blf[nt]);
                    mma_tf32(acc[mt][nt], ah, bhf[nt]);
                }
            }
        }
        __syncthreads();
    }

    #pragma unroll
    for (int mt = 0; mt < 2; mt++) {
        #pragma unroll
        for (int nt = 0; nt < 2; nt++) {
            int gc0 = wn*16 + nt*8 + 2*tig;
            #pragma unroll
            for (int half = 0; half < 2; half++) {
                int gr = row0 + wm*32 + mt*16 + g + half*8;
                if (gr >= N) continue;
                uint32_t hw, lw2;
                split2_bf16(acc[mt][nt][half*2], acc[mt][nt][half*2 + 1], hw, lw2);
                size_t off = cbase + (size_t)gr*DD + gc0;
                *(uint32_t*)(oh + off) = hw;
                *(uint32_t*)(ol + off) = lw2;
            }
        }
    }
}

// ---------------- SIMT GEMM (tiny shapes: N=1 predictor head, class head) -------
__global__ void gemm_kernel(const float* __restrict__ A, const float* __restrict__ W,
                            const float* __restrict__ bias, const float* __restrict__ resid,
                            float* __restrict__ C, int M, int N, int K, int act)
{
    __shared__ float As[16][65];
    __shared__ float Ws[16][65];
    int tx = threadIdx.x, ty = threadIdx.y;
    int tid = ty*16 + tx;
    int row0 = blockIdx.y*64, col0 = blockIdx.x*64;
    float acc[4][4] = {};
    for (int k0 = 0; k0 < K; k0 += 16) {
        #pragma unroll
        for (int i = 0; i < 4; i++) {
            int idx = tid + i*256;
            int r = idx >> 4;
            int c = idx & 15;
            int gr = row0 + r;
            As[c][r] = (gr < M) ? A[(size_t)gr*K + k0 + c] : 0.f;
            int wr = col0 + r;
            Ws[c][r] = (wr < N) ? W[(size_t)wr*K + k0 + c] : 0.f;
        }
        __syncthreads();
        #pragma unroll
        for (int kk = 0; kk < 16; kk++) {
            float a[4], bb[4];
            #pragma unroll
            for (int i = 0; i < 4; i++) a[i] = As[kk][ty*4+i];
            #pragma unroll
            for (int j = 0; j < 4; j++) bb[j] = Ws[kk][tx*4+j];
            #pragma unroll
            for (int i = 0; i < 4; i++)
                #pragma unroll
                for (int j = 0; j < 4; j++)
                    acc[i][j] = fmaf(a[i], bb[j], acc[i][j]);
        }
        __syncthreads();
    }
    #pragma unroll
    for (int i = 0; i < 4; i++) {
        int gr = row0 + ty*4 + i;
        if (gr >= M) continue;
        #pragma unroll
        for (int j = 0; j < 4; j++) {
            int gc = col0 + tx*4 + j;
            if (gc >= N) continue;
            float v = acc[i][j] + bias[gc];
            if (act == 1) v = gelu_f(v);
            if (resid) v += resid[(size_t)gr*N + gc];
            C[(size_t)gr*N + gc] = v;
        }
    }
}

// ---------------- LayerNorm: out = fp32 (dstf) or bf16 pair (dsth/dstl) --------
__global__ void ln_kernel(const float* __restrict__ src, float* __restrict__ dstf,
                          bf16* __restrict__ dsth, bf16* __restrict__ dstl,
                          const float* __restrict__ gamma, const float* __restrict__ beta,
                          int n_src_tokens, int toks_out, int tok_off)
{
    int r = blockIdx.x;
    int b = r / toks_out;
    int n = r % toks_out + tok_off;
    const float* x = src + ((size_t)b*n_src_tokens + n)*DD;
    int tid = threadIdx.x;                 // 256
    float v[3];
    float s = 0.f, s2 = 0.f;
    #pragma unroll
    for (int i = 0; i < 3; i++) { v[i] = x[tid + i*256]; s += v[i]; s2 += v[i]*v[i]; }
    __shared__ float sh1[8], sh2[8];
    #pragma unroll
    for (int o = 16; o > 0; o >>= 1) {
        s  += __shfl_xor_sync(0xffffffffu, s,  o);
        s2 += __shfl_xor_sync(0xffffffffu, s2, o);
    }
    if ((tid & 31) == 0) { sh1[tid>>5] = s; sh2[tid>>5] = s2; }
    __syncthreads();
    float ts = 0.f, ts2 = 0.f;
    #pragma unroll
    for (int w = 0; w < 8; w++) { ts += sh1[w]; ts2 += sh2[w]; }
    float mean = ts * (1.f/768.f);
    float var  = ts2 * (1.f/768.f) - mean*mean;
    float rstd = rsqrtf(var + 1e-6f);
    size_t ob = (size_t)r*DD;
    #pragma unroll
    for (int i = 0; i < 3; i++) {
        int c = tid + i*256;
        float y = (v[i] - mean) * rstd * gamma[c] + beta[c];
        if (dstf) dstf[ob + c] = y;
        else      split1(y, dsth[ob + c], dstl[ob + c]);
    }
}

// ---------------- predictor helpers ----------------
__global__ void globmean_kernel(const float* __restrict__ hidden, float* __restrict__ glob, int L)
{
    int b = blockIdx.x;
    int c = threadIdx.x;                   // 384
    float s = 0.f;
    for (int l = 0; l < L; l++) s += hidden[((size_t)b*L + l)*DD + 384 + c];
    glob[b*384 + c] = s / (float)L;
}

// combine -> bf16 pair
__global__ void combine_kernel(const float* __restrict__ hidden, const float* __restrict__ glob,
                               bf16* __restrict__ h2h, bf16* __restrict__ h2l, int L)
{
    int i = blockIdx.x * blockDim.x + threadIdx.x;
    int total = BB*L*DD;
    if (i >= total) return;
    int c = i % DD;
    int r = i / DD;
    int b = r / L;
    float v = (c < 384) ? hidden[i] : glob[b*384 + (c - 384)];
    split1(v, h2h[i], h2l[i]);
}

// exact jax top_k order via rank counting (score desc, index asc tie-break).
__global__ void topk_kernel(const float* __restrict__ score, int* __restrict__ idx, int L, int k)
{
    int b = blockIdx.x;
    __shared__ float s[LMAX];
    int t = threadIdx.x;                   // 256
    for (int j = t; j < L; j += blockDim.x) s[j] = score[b*L + j];
    __syncthreads();
    if (t < L) {
        float my = s[t];
        int rank = 0;
        for (int j = 0; j < L; j++) {
            float v = s[j];
            rank += (v > my) || (v == my && j < t);
        }
        if (rank < k) idx[b*LMAX + rank] = t;
    }
}

__global__ void gather_kernel(const float* __restrict__ tin, const int* __restrict__ idx,
                              float* __restrict__ tout, int Nin, int Nout)
{
    int i = blockIdx.x * blockDim.x + threadIdx.x;
    int total = BB*Nout*DD;
    if (i >= total) return;
    int c = i % DD;
    int r = i / DD;
    int b = r / Nout;
    int j = r % Nout;
    int n = (j == 0) ? 0 : (1 + idx[b*LMAX + (j - 1)]);
    tout[i] = tin[((size_t)b*Nin + n)*DD + c];
}

// ---------------- host orchestration ----------------
static inline void launch_gemm2(const bf16* Ah, const bf16* Al,
                                const bf16* Wh, const bf16* Wl,
                                const float* bias, const float* resid,
                                float* Cf, bf16* Ch, bf16* Cl,
                                int M, int N, int K, int act)
{
    dim3 grid((N + 127) / 128, (M + 127) / 128);
    gemm_tc2_kernel<<<grid, 256>>>(Ah, Al, Wh, Wl, bias, resid, Cf, Ch, Cl, M, N, K, act);
}

static inline void launch_gemm(const float* A, const float* W, const float* bias,
                               const float* resid, float* C, int M, int N, int K, int act)
{
    dim3 grid((N + 63) / 64, (M + 63) / 64);
    dim3 block(16, 16);
    gemm_kernel<<<grid, block>>>(A, W, bias, resid, C, M, N, K, act);
}

static inline void launch_split(const float* in, bf16* hi, bf16* lo, int n)
{
    int n4 = n / 4;
    split_kernel<<<(n4 + 255) / 256, 256>>>(in, hi, lo, n4);
}

extern "C" void kernel_launch(void* const* d_in, const int* in_sizes, int n_in,
                              void* d_out, int out_size)
{
    const float* x       = (const float*)d_in[0];
    const float* patch_w = (const float*)d_in[1];
    const float* patch_b = (const float*)d_in[2];
    const float* cls_tok = (const float*)d_in[3];
    const float* pos     = (const float*)d_in[4];
    const float* ln1_g   = (const float*)d_in[5];
    const float* ln1_b   = (const float*)d_in[6];
    const float* qkv_w   = (const float*)d_in[7];
    const float* qkv_b   = (const float*)d_in[8];
    const float* proj_w  = (const float*)d_in[9];
    const float* proj_b  = (const float*)d_in[10];
    const float* ln2_g   = (const float*)d_in[11];
    const float* ln2_b   = (const float*)d_in[12];
    const float* fc1_w   = (const float*)d_in[13];
    const float* fc1_b   = (const float*)d_in[14];
    const float* fc2_w   = (const float*)d_in[15];
    const float* fc2_b   = (const float*)d_in[16];
    const float* pln_g   = (const float*)d_in[17];
    const float* pln_b   = (const float*)d_in[18];
    const float* pin_w   = (const float*)d_in[19];
    const float* pin_b   = (const float*)d_in[20];
    const float* pw1     = (const float*)d_in[21];
    const float* pb1     = (const float*)d_in[22];
    const float* pw2     = (const float*)d_in[23];
    const float* pb2     = (const float*)d_in[24];
    const float* pw3     = (const float*)d_in[25];
    const float* pb3     = (const float*)d_in[26];
    const float* norm_g  = (const float*)d_in[27];
    const float* norm_b  = (const float*)d_in[28];
    const float* head_w  = (const float*)d_in[29];
    const float* head_b  = (const float*)d_in[30];
    (void)in_sizes; (void)n_in; (void)out_size;

    void* p;
    cudaGetSymbolAddress(&p, g_t0);    float* t0    = (float*)p;
    cudaGetSymbolAddress(&p, g_t1);    float* t1    = (float*)p;
    cudaGetSymbolAddress(&p, g_qkv);   float* qkvb  = (float*)p;
    cudaGetSymbolAddress(&p, g_pa);    float* pa    = (float*)p;
    cudaGetSymbolAddress(&p, g_pb);    float* pbuf  = (float*)p;
    cudaGetSymbolAddress(&p, g_glob);  float* glob  = (float*)p;
    cudaGetSymbolAddress(&p, g_score); float* score = (float*)p;
    cudaGetSymbolAddress(&p, g_idx);   int*   gidx  = (int*)p;
    cudaGetSymbolAddress(&p, g_cls);   float* clsb  = (float*)p;
    cudaGetSymbolAddress(&p, g_att);   float* attb  = (float*)p;

    cudaGetSymbolAddress(&p, g_lnh);   bf16* lnh  = (bf16*)p;
    cudaGetSymbolAddress(&p, g_lnl);   bf16* lnl  = (bf16*)p;
    cudaGetSymbolAddress(&p, g_aoh);   bf16* aoh  = (bf16*)p;
    cudaGetSymbolAddress(&p, g_aol);   bf16* aol  = (bf16*)p;
    cudaGetSymbolAddress(&p, g_mlph);  bf16* mlph = (bf16*)p;
    cudaGetSymbolAddress(&p, g_mlpl);  bf16* mlpl = (bf16*)p;
    cudaGetSymbolAddress(&p, g_imh);   bf16* imh  = (bf16*)p;
    cudaGetSymbolAddress(&p, g_iml);   bf16* iml  = (bf16*)p;
    cudaGetSymbolAddress(&p, g_ppbh);  bf16* ppbh = (bf16*)p;
    cudaGetSymbolAddress(&p, g_ppbl);  bf16* ppbl = (bf16*)p;

    cudaGetSymbolAddress(&p, g_qkvwh);  bf16* qkvwh  = (bf16*)p;
    cudaGetSymbolAddress(&p, g_qkvwl);  bf16* qkvwl  = (bf16*)p;
    cudaGetSymbolAddress(&p, g_projwh); bf16* projwh = (bf16*)p;
    cudaGetSymbolAddress(&p, g_projwl); bf16* projwl = (bf16*)p;
    cudaGetSymbolAddress(&p, g_fc1wh);  bf16* fc1wh  = (bf16*)p;
    cudaGetSymbolAddress(&p, g_fc1wl);  bf16* fc1wl  = (bf16*)p;
    cudaGetSymbolAddress(&p, g_fc2wh);  bf16* fc2wh  = (bf16*)p;
    cudaGetSymbolAddress(&p, g_fc2wl);  bf16* fc2wl  = (bf16*)p;
    cudaGetSymbolAddress(&p, g_patchwh); bf16* patchwh = (bf16*)p;
    cudaGetSymbolAddress(&p, g_patchwl); bf16* patchwl = (bf16*)p;
    cudaGetSymbolAddress(&p, g_pinwh);  bf16* pinwh  = (bf16*)p;
    cudaGetSymbolAddress(&p, g_pinwl);  bf16* pinwl  = (bf16*)p;
    cudaGetSymbolAddress(&p, g_pw1h);   bf16* pw1h   = (bf16*)p;
    cudaGetSymbolAddress(&p, g_pw1l);   bf16* pw1l   = (bf16*)p;
    cudaGetSymbolAddress(&p, g_pw2h);   bf16* pw2h   = (bf16*)p;
    cudaGetSymbolAddress(&p, g_pw2l);   bf16* pw2l   = (bf16*)p;

    // weight splits (every replay; ~0.2 ms bandwidth-bound)
    launch_split(qkv_w,   qkvwh,  qkvwl,  SZ_QKVW);
    launch_split(proj_w,  projwh, projwl, SZ_PROJW);
    launch_split(fc1_w,   fc1wh,  fc1wl,  SZ_FC1W);
    launch_split(fc2_w,   fc2wh,  fc2wl,  SZ_FC2W);
    launch_split(patch_w, patchwh, patchwl, SZ_PATCHW);
    launch_split(pin_w,   pinwh,  pinwl,  SZ_PINW);
    launch_split(pw1,     pw1h,   pw1l,   SZ_PW1);
    launch_split(pw2,     pw2h,   pw2l,   SZ_PW2);

    // patch embedding
    { int total = BB*LMAX*DD; im2col_kernel<<<(total + 255)/256, 256>>>(x, imh, iml); }
    launch_gemm2(imh, iml, patchwh, patchwl, patch_b, nullptr, pbuf, nullptr, nullptr,
                 BB*LMAX, DD, DD, 0);
    { int total = BB*NMAX*DD; assemble_kernel<<<(total + 255)/256, 256>>>(pbuf, cls_tok, pos, t0); }

    float* ta = t0;
    float* tb = t1;
    int N = NMAX;
    const int kkeep[3] = {138, 97, 68};

    for (int i = 0; i < 12; i++) {
        int s = (i == 3) ? 0 : (i == 6) ? 1 : (i == 9) ? 2 : -1;
        if (s >= 0) {
            int L = N - 1;
            int M = BB * L;
            ln_kernel<<<M, 256>>>(ta, nullptr, imh, iml, pln_g + s*DD, pln_b + s*DD, N, L, 1);
            launch_gemm2(imh, iml, pinwh + (size_t)s*DD*DD, pinwl + (size_t)s*DD*DD,
                         pin_b + s*DD, nullptr, pbuf, nullptr, nullptr, M, DD, DD, 1);
            globmean_kernel<<<BB, 384>>>(pbuf, glob, L);
            { int total = M*DD; combine_kernel<<<(total + 255)/256, 256>>>(pbuf, glob, imh, iml, L); }
            launch_gemm2(imh, iml, pw1h + (size_t)s*384*DD, pw1l + (size_t)s*384*DD,
                         pb1 + s*384, nullptr, nullptr, ppbh, ppbl, M, 384, DD, 1);
            launch_gemm2(ppbh, ppbl, pw2h + (size_t)s*192*384, pw2l + (size_t)s*192*384,
                         pb2 + s*192, nullptr, pa, nullptr, nullptr, M, 192, 384, 1);
            launch_gemm(pa, pw3 + (size_t)s*192, pb3 + s, nullptr, score, M, 1, 192, 0);
            topk_kernel<<<BB, 256>>>(score, gidx, L, kkeep[s]);
            int Nn = kkeep[s] + 1;
            { int total = BB*Nn*DD; gather_kernel<<<(total + 255)/256, 256>>>(ta, gidx, tb, N, Nn); }
            float* tmp = ta; ta = tb; tb = tmp;
            N = Nn;
        }
        int M = BB * N;
        int ntile = (N + 63) / 64;
        ln_kernel<<<M, 256>>>(ta, nullptr, lnh, lnl, ln1_g + i*DD, ln1_b + i*DD, N, N, 0);
        launch_gemm2(lnh, lnl, qkvwh + (size_t)i*2304*DD, qkvwl + (size_t)i*2304*DD,
                     qkv_b + i*2304, nullptr, qkvb, nullptr, nullptr, M, 2304, DD, 0);
        {
            dim3 gqk(ntile, ntile, BB*NHD);
            attn_qk_kernel<<<gqk, 256>>>(qkvb, attb, N);
            int rows = BB*NHD*N;
            attn_softmax_kernel<<<(rows + 3)/4, 128>>>(attb, N, rows);
            dim3 gpv(1, ntile, BB*NHD);
            attn_pv_kernel<<<gpv, 256>>>(attb, qkvb, aoh, aol, N);
        }
        launch_gemm2(aoh, aol, projwh + (size_t)i*DD*DD, projwl + (size_t)i*DD*DD,
                     proj_b + i*DD, ta, tb, nullptr, nullptr, M, DD, DD, 0);
        ln_kernel<<<M, 256>>>(tb, nullptr, lnh, lnl, ln2_g + i*DD, ln2_b + i*DD, N, N, 0);
        launch_gemm2(lnh, lnl, fc1wh + (size_t)i*3072*DD, fc1wl + (size_t)i*3072*DD,
                     fc1_b + i*3072, nullptr, nullptr, mlph, mlpl, M, 3072, DD, 1);
        launch_gemm2(mlph, mlpl, fc2wh + (size_t)i*DD*3072, fc2wl + (size_t)i*DD*3072,
                     fc2_b + i*DD, tb, ta, nullptr, nullptr, M, DD, 3072, 0);
    }

    // final LN on cls token + classification head
    ln_kernel<<<BB, 256>>>(ta, clsb, nullptr, nullptr, norm_g, norm_b, N, 1, 0);
    launch_gemm(clsb, head_w, head_b, nullptr, (float*)d_out, BB, 1000, DD, 0);
}

// round 12
// speedup vs baseline: 1.3246x; 1.0874x over previous
#include <cuda_runtime.h>
#include <cuda_bf16.h>
#include <math.h>
#include <stdint.h>

#define BB   32
#define DD   768
#define NHD  12
#define HD   64
#define NMAX 197
#define LMAX 196
#define ATTN_SCALE 0.125f

typedef __nv_bfloat16 bf16;

// ---------------- weight pair sizes ----------------
#define SZ_QKVW  (12*2304*768)
#define SZ_PROJW (12*768*768)
#define SZ_FC1W  (12*3072*768)
#define SZ_FC2W  (12*3072*768)
#define SZ_PATCHW (768*768)
#define SZ_PINW  (3*768*768)
#define SZ_PW1   (3*384*768)
#define SZ_PW2   (3*192*384)

// ---------------- scratch (device globals; no allocation allowed) ----------------
__device__ float g_t0[BB*NMAX*DD];
__device__ float g_t1[BB*NMAX*DD];
__device__ float g_qkv[BB*NMAX*2304];
__device__ float g_pa[BB*LMAX*DD];
__device__ float g_pb[BB*LMAX*DD];
__device__ float g_glob[BB*384];
__device__ float g_score[BB*LMAX];
__device__ int   g_idx[BB*LMAX];
__device__ float g_cls[BB*DD];
__device__ float g_att[(size_t)BB*NHD*NMAX*NMAX];

// bf16 hi/lo activation pairs (16B-aligned for cp.async)
__device__ __align__(16) bf16 g_lnh[BB*NMAX*DD],  g_lnl[BB*NMAX*DD];
__device__ __align__(16) bf16 g_aoh[BB*NMAX*DD],  g_aol[BB*NMAX*DD];
__device__ __align__(16) bf16 g_mlph[BB*NMAX*3072], g_mlpl[BB*NMAX*3072];
__device__ __align__(16) bf16 g_imh[BB*LMAX*DD],  g_iml[BB*LMAX*DD];
__device__ __align__(16) bf16 g_ppbh[BB*LMAX*384], g_ppbl[BB*LMAX*384];

// bf16 hi/lo weight pairs (16B-aligned for cp.async)
__device__ __align__(16) bf16 g_qkvwh[SZ_QKVW],  g_qkvwl[SZ_QKVW];
__device__ __align__(16) bf16 g_projwh[SZ_PROJW], g_projwl[SZ_PROJW];
__device__ __align__(16) bf16 g_fc1wh[SZ_FC1W],  g_fc1wl[SZ_FC1W];
__device__ __align__(16) bf16 g_fc2wh[SZ_FC2W],  g_fc2wl[SZ_FC2W];
__device__ __align__(16) bf16 g_patchwh[SZ_PATCHW], g_patchwl[SZ_PATCHW];
__device__ __align__(16) bf16 g_pinwh[SZ_PINW],  g_pinwl[SZ_PINW];
__device__ __align__(16) bf16 g_pw1h[SZ_PW1],    g_pw1l[SZ_PW1];
__device__ __align__(16) bf16 g_pw2h[SZ_PW2],    g_pw2l[SZ_PW2];

__device__ __forceinline__ float gelu_f(float x) {
    return 0.5f * x * (1.f + erff(x * 0.70710678118654752440f));
}

__device__ __forceinline__ void split1(float v, bf16& h, bf16& l) {
    h = __float2bfloat16(v);
    l = __float2bfloat16(v - __bfloat162float(h));
}

// split two floats into packed bf16 hi pair + lo pair
__device__ __forceinline__ void split2_bf16(float v0, float v1, uint32_t& hi, uint32_t& lo) {
    bf16 h0 = __float2bfloat16(v0);
    bf16 h1 = __float2bfloat16(v1);
    float r0 = v0 - __bfloat162float(h0);
    float r1 = v1 - __bfloat162float(h1);
    bf16 l0 = __float2bfloat16(r0);
    bf16 l1 = __float2bfloat16(r1);
    hi = (uint32_t)__bfloat16_as_ushort(h0) | ((uint32_t)__bfloat16_as_ushort(h1) << 16);
    lo = (uint32_t)__bfloat16_as_ushort(l0) | ((uint32_t)__bfloat16_as_ushort(l1) << 16);
}

// ---------------- weight split: fp32 -> bf16 hi/lo pairs ----------------
__global__ void split_kernel(const float* __restrict__ in, bf16* __restrict__ hi,
                             bf16* __restrict__ lo, int n4)
{
    int i = blockIdx.x * blockDim.x + threadIdx.x;
    if (i >= n4) return;
    float4 v = ((const float4*)in)[i];
    uint32_t h0, l0, h1, l1;
    split2_bf16(v.x, v.y, h0, l0);
    split2_bf16(v.z, v.w, h1, l1);
    ((uint32_t*)hi)[i*2]   = h0;
    ((uint32_t*)hi)[i*2+1] = h1;
    ((uint32_t*)lo)[i*2]   = l0;
    ((uint32_t*)lo)[i*2+1] = l1;
}

// ---------------- im2col for patch embedding (writes bf16 pair) ----------------
__global__ void im2col_kernel(const float* __restrict__ x, bf16* __restrict__ ph,
                              bf16* __restrict__ pl) {
    int i = blockIdx.x * blockDim.x + threadIdx.x;
    const int total = BB*LMAX*DD;
    if (i >= total) return;
    int c = i % DD;
    int r = i / DD;
    int b = r / LMAX;
    int l = r % LMAX;
    int gy = l / 14, gx = l % 14;
    int ch = c / 256, rem = c % 256, py = rem / 16, px = rem % 16;
    float v = x[(((size_t)b*3 + ch)*224 + gy*16 + py)*224 + gx*16 + px];
    split1(v, ph[i], pl[i]);
}

// assemble t = [cls | patches] + pos
__global__ void assemble_kernel(const float* __restrict__ pe, const float* __restrict__ cls,
                                const float* __restrict__ pos, float* __restrict__ t) {
    int i = blockIdx.x * blockDim.x + threadIdx.x;
    const int total = BB*NMAX*DD;
    if (i >= total) return;
    int d = i % DD;
    int n = (i / DD) % NMAX;
    int b = i / (DD*NMAX);
    float v = (n == 0) ? cls[d] : pe[((size_t)b*LMAX + (n-1))*DD + d];
    t[i] = v + pos[n*DD + d];
}

// =====================================================================
// mma helpers
// =====================================================================
#define SK 20    // attention smem stride (floats)
#define SKB 12   // gemm smem stride (words); (r*12+tig) mod 32 hits all banks

__device__ __forceinline__ uint32_t f2tf(float f) {
    uint32_t u;
    asm("cvt.rna.tf32.f32 %0, %1;" : "=r"(u) : "f"(f));
    return u;
}

__device__ __forceinline__ void mma_tf32(float d[4], const uint32_t a[4], const uint32_t b[2]) {
    asm volatile(
        "mma.sync.aligned.m16n8k8.row.col.f32.tf32.tf32.f32 "
        "{%0,%1,%2,%3}, {%4,%5,%6,%7}, {%8,%9}, {%0,%1,%2,%3};\n"
        : "+f"(d[0]), "+f"(d[1]), "+f"(d[2]), "+f"(d[3])
        : "r"(a[0]), "r"(a[1]), "r"(a[2]), "r"(a[3]), "r"(b[0]), "r"(b[1]));
}

__device__ __forceinline__ void mma_bf16(float d[4], const uint32_t a[4], const uint32_t b[2]) {
    asm volatile(
        "mma.sync.aligned.m16n8k16.row.col.f32.bf16.bf16.f32 "
        "{%0,%1,%2,%3}, {%4,%5,%6,%7}, {%8,%9}, {%0,%1,%2,%3};\n"
        : "+f"(d[0]), "+f"(d[1]), "+f"(d[2]), "+f"(d[3])
        : "r"(a[0]), "r"(a[1]), "r"(a[2]), "r"(a[3]), "r"(b[0]), "r"(b[1]));
}

// ---------------- cp.async helpers ----------------
__device__ __forceinline__ void cpa16(uint32_t sa, const void* g, bool valid) {
    int sz = valid ? 16 : 0;
    asm volatile("cp.async.cg.shared.global [%0], [%1], 16, %2;"
                 :: "r"(sa), "l"(g), "r"(sz));
}
#define CP_COMMIT() asm volatile("cp.async.commit_group;")
#define CP_WAIT1()  asm volatile("cp.async.wait_group 1;")

// =====================================================================
// Tensor-core GEMM v4: C = act(A[M,K] @ W[N,K]^T + bias) (+resid)
// Pre-split bf16 hi/lo pairs. 3-stage cp.async pipeline, BK=16,
// ONE __syncthreads per k-tile (reuse distance 3 makes it sufficient).
// 128x128x16 CTA tile, 256 threads, warp grid 2x4, warp tile 64x32.
// Dynamic smem: 3 stages x 4 arrays x 128 x SKB words = 73728 B.
// =====================================================================
#define GEMM_STAGE_WORDS (4*128*SKB)     // 6144 words per stage
#define GEMM_ARR_WORDS   (128*SKB)       // 1536 words per array
#define GEMM_SMEM_BYTES  (3*GEMM_STAGE_WORDS*4)

__global__ __launch_bounds__(256)
void gemm_tc2_kernel(const bf16* __restrict__ Ahg, const bf16* __restrict__ Alg,
                     const bf16* __restrict__ Whg, const bf16* __restrict__ Wlg,
                     const float* __restrict__ bias, const float* __restrict__ resid,
                     float* __restrict__ Cf, bf16* __restrict__ Ch, bf16* __restrict__ Cl,
                     int M, int N, int K, int act)
{
    extern __shared__ __align__(16) uint32_t smem[];   // [3][4][128][SKB]

    int tid = threadIdx.x;
    int lane = tid & 31, w = tid >> 5;
    int wm = w >> 2, wn = w & 3;          // warp grid 2x4
    int g = lane >> 2, tig = lane & 3;    // mma quad coords
    int row0 = blockIdx.y * 128, col0 = blockIdx.x * 128;

    float acc[4][4][4];
    #pragma unroll
    for (int i = 0; i < 4; i++)
        #pragma unroll
        for (int j = 0; j < 4; j++)
            #pragma unroll
            for (int q = 0; q < 4; q++) acc[i][j][q] = 0.f;

    // loader mapping: 2 threads per row, each 16B (8 bf16)
    int lrow = tid >> 1;          // 0..127
    int lhalf = tid & 1;          // 0/1
    int gra = row0 + lrow; bool va = gra < M; if (!va) gra = 0;
    int wra = col0 + lrow; bool vb = wra < N; if (!vb) wra = 0;
    uint32_t smem_base = (uint32_t)__cvta_generic_to_shared(smem);
    uint32_t soff = (uint32_t)((lrow*SKB + lhalf*4) * 4);   // byte offset in array

    int ktiles = K >> 4;

    // issue_tile lambda
    auto issue_tile = [&](int kt, int s) {
        int k0 = (kt << 4) + lhalf*8;
        uint32_t sb = smem_base + (uint32_t)(s*GEMM_STAGE_WORDS*4) + soff;
        cpa16(sb + 0*GEMM_ARR_WORDS*4, Ahg + (size_t)gra*K + k0, va);
        cpa16(sb + 1*GEMM_ARR_WORDS*4, Alg + (size_t)gra*K + k0, va);
        cpa16(sb + 2*GEMM_ARR_WORDS*4, Whg + (size_t)wra*K + k0, vb);
        cpa16(sb + 3*GEMM_ARR_WORDS*4, Wlg + (size_t)wra*K + k0, vb);
    };

    issue_tile(0, 0); CP_COMMIT();
    if (ktiles > 1) issue_tile(1, 1);
    CP_COMMIT();

    for (int kt = 0; kt < ktiles; kt++) {
        CP_WAIT1();               // own-thread groups for tile kt complete
        __syncthreads();          // publish tile kt; orders compute(kt-1) before reissue
        if (kt + 2 < ktiles) issue_tile(kt + 2, (kt + 2) % 3);
        CP_COMMIT();

        const uint32_t* Ah = smem + (kt % 3)*GEMM_STAGE_WORDS;
        const uint32_t* Al = Ah + GEMM_ARR_WORDS;
        const uint32_t* Bh = Ah + 2*GEMM_ARR_WORDS;
        const uint32_t* Bl = Ah + 3*GEMM_ARR_WORDS;

        uint32_t bhf[4][2], blf[4][2];
        #pragma unroll
        for (int nt = 0; nt < 4; nt++) {
            int n = (wn*32 + nt*8 + g) * SKB;
            bhf[nt][0] = Bh[n + tig];
            bhf[nt][1] = Bh[n + tig + 4];
            blf[nt][0] = Bl[n + tig];
            blf[nt][1] = Bl[n + tig + 4];
        }
        #pragma unroll
        for (int mt = 0; mt < 4; mt++) {
            int r  = (wm*64 + mt*16 + g) * SKB;
            int r8 = r + 8*SKB;
            uint32_t ah[4], al[4];
            ah[0] = Ah[r + tig];
            ah[1] = Ah[r8 + tig];
            ah[2] = Ah[r + tig + 4];
            ah[3] = Ah[r8 + tig + 4];
            al[0] = Al[r + tig];
            al[1] = Al[r8 + tig];
            al[2] = Al[r + tig + 4];
            al[3] = Al[r8 + tig + 4];
            #pragma unroll
            for (int nt = 0; nt < 4; nt++) {
                mma_bf16(acc[mt][nt], al, bhf[nt]);   // lo*hi
                mma_bf16(acc[mt][nt], ah, blf[nt]);   // hi*lo
                mma_bf16(acc[mt][nt], ah, bhf[nt]);   // hi*hi
            }
        }
    }

    // epilogue
    #pragma unroll
    for (int mt = 0; mt < 4; mt++) {
        #pragma unroll
        for (int nt = 0; nt < 4; nt++) {
            int gc0 = col0 + wn*32 + nt*8 + 2*tig;
            #pragma unroll
            for (int half = 0; half < 2; half++) {
                int gr = row0 + wm*64 + mt*16 + g + half*8;
                if (gr >= M) continue;
                if (Cf) {
                    #pragma unroll
                    for (int j = 0; j < 2; j++) {
                        int gc = gc0 + j;
                        if (gc >= N) continue;
                        float v = acc[mt][nt][half*2 + j] + bias[gc];
                        if (act == 1) v = gelu_f(v);
                        if (resid) v += resid[(size_t)gr*N + gc];
                        Cf[(size_t)gr*N + gc] = v;
                    }
                } else {
                    if (gc0 + 1 >= N) continue;
                    float v0 = acc[mt][nt][half*2 + 0] + bias[gc0];
                    float v1 = acc[mt][nt][half*2 + 1] + bias[gc0+1];
                    if (act == 1) { v0 = gelu_f(v0); v1 = gelu_f(v1); }
                    uint32_t hw, lw2;
                    split2_bf16(v0, v1, hw, lw2);
                    *(uint32_t*)(Ch + (size_t)gr*N + gc0) = hw;
                    *(uint32_t*)(Cl + (size_t)gr*N + gc0) = lw2;
                }
            }
        }
    }
}

// =====================================================================
// Batched attention, stage 1: scores = Q @ K^T per (b,h). 3xTF32.
// =====================================================================
__global__ __launch_bounds__(256)
void attn_qk_kernel(const float* __restrict__ qkv, float* __restrict__ att, int N)
{
    __shared__ __align__(16) float Ah[64][SK];
    __shared__ __align__(16) float Al[64][SK];
    __shared__ __align__(16) float Bh[64][SK];
    __shared__ __align__(16) float Bl[64][SK];

    int tid = threadIdx.x;
    int lane = tid & 31, w = tid >> 5;
    int wm = w >> 2, wn = w & 3;
    int g = lane >> 2, tig = lane & 3;
    int bh = blockIdx.z;
    int b = bh / NHD, h = bh % NHD;
    const float* Q  = qkv + (size_t)b*N*2304 + h*HD;
    const float* Kp = qkv + (size_t)b*N*2304 + 768 + h*HD;
    float* C = att + (size_t)bh*N*N;
    int row0 = blockIdx.y * 64, col0 = blockIdx.x * 64;

    float acc[2][2][4];
    #pragma unroll
    for (int i = 0; i < 2; i++)
        #pragma unroll
        for (int j = 0; j < 2; j++)
            #pragma unroll
            for (int q = 0; q < 4; q++) acc[i][j][q] = 0.f;

    int ldr = tid >> 2;
    int ldc = (tid & 3) * 4;
    const float4 z4 = make_float4(0.f, 0.f, 0.f, 0.f);

    #pragma unroll
    for (int kt = 0; kt < 4; kt++) {
        int k0 = kt * 16;
        {
            int gr = row0 + ldr;
            float4 va = (gr < N) ? *(const float4*)(Q + (size_t)gr*2304 + k0 + ldc) : z4;
            int wr = col0 + ldr;
            float4 vb = (wr < N) ? *(const float4*)(Kp + (size_t)wr*2304 + k0 + ldc) : z4;
            float av[4] = {va.x, va.y, va.z, va.w};
            float bv[4] = {vb.x, vb.y, vb.z, vb.w};
            float4 ah4, al4, bh4, bl4;
            float* ahp = &ah4.x; float* alp = &al4.x;
            float* bhp = &bh4.x; float* blp = &bl4.x;
            #pragma unroll
            for (int j = 0; j < 4; j++) {
                uint32_t hh = f2tf(av[j]);
                ahp[j] = __uint_as_float(hh);
                alp[j] = av[j] - ahp[j];
                uint32_t hb = f2tf(bv[j]);
                bhp[j] = __uint_as_float(hb);
                blp[j] = bv[j] - bhp[j];
            }
            *(float4*)&Ah[ldr][ldc] = ah4;
            *(float4*)&Al[ldr][ldc] = al4;
            *(float4*)&Bh[ldr][ldc] = bh4;
            *(float4*)&Bl[ldr][ldc] = bl4;
        }
        __syncthreads();
        #pragma unroll
        for (int ks = 0; ks < 2; ks++) {
            int k = ks*8 + tig;
            uint32_t bhf[2][2], blf[2][2];
            #pragma unroll
            for (int nt = 0; nt < 2; nt++) {
                int n = wn*16 + nt*8 + g;
                bhf[nt][0] = __float_as_uint(Bh[n][k]);
                bhf[nt][1] = __float_as_uint(Bh[n][k+4]);
                blf[nt][0] = __float_as_uint(Bl[n][k]);
                blf[nt][1] = __float_as_uint(Bl[n][k+4]);
            }
            #pragma unroll
            for (int mt = 0; mt < 2; mt++) {
                int r = wm*32 + mt*16 + g;
                uint32_t ah[4], al[4];
                ah[0] = __float_as_uint(Ah[r][k]);
                ah[1] = __float_as_uint(Ah[r+8][k]);
                ah[2] = __float_as_uint(Ah[r][k+4]);
                ah[3] = __float_as_uint(Ah[r+8][k+4]);
                al[0] = __float_as_uint(Al[r][k]);
                al[1] = __float_as_uint(Al[r+8][k]);
                al[2] = __float_as_uint(Al[r][k+4]);
                al[3] = __float_as_uint(Al[r+8][k+4]);
                #pragma unroll
                for (int nt = 0; nt < 2; nt++) {
                    mma_tf32(acc[mt][nt], al, bhf[nt]);
                    mma_tf32(acc[mt][nt], ah, blf[nt]);
                    mma_tf32(acc[mt][nt], ah, bhf[nt]);
                }
            }
        }
        __syncthreads();
    }

    #pragma unroll
    for (int mt = 0; mt < 2; mt++) {
        #pragma unroll
        for (int nt = 0; nt < 2; nt++) {
            int gc0 = col0 + wn*16 + nt*8 + 2*tig;
            #pragma unroll
            for (int half = 0; half < 2; half++) {
                int gr = row0 + wm*32 + mt*16 + g + half*8;
                if (gr >= N) continue;
                #pragma unroll
                for (int j = 0; j < 2; j++) {
                    int gc = gc0 + j;
                    if (gc < N) C[(size_t)gr*N + gc] = acc[mt][nt][half*2 + j];
                }
            }
        }
    }
}

// =====================================================================
// Batched attention, stage 2: in-place row softmax of scaled scores.
// =====================================================================
__global__ void attn_softmax_kernel(float* __restrict__ att, int N, int rows)
{
    int row = blockIdx.x * 4 + (threadIdx.x >> 5);
    if (row >= rows) return;
    int lane = threadIdx.x & 31;
    float* p = att + (size_t)row * N;
    float v[7];
    int cnt = 0;
    float m = -1e30f;
    for (int j = lane; j < N; j += 32) { float s = p[j]; v[cnt++] = s; m = fmaxf(m, s); }
    #pragma unroll
    for (int o = 16; o > 0; o >>= 1) m = fmaxf(m, __shfl_xor_sync(0xffffffffu, m, o));
    float sum = 0.f;
    #pragma unroll
    for (int q = 0; q < 7; q++) {
        if (q < cnt) { v[q] = expf((v[q] - m) * ATTN_SCALE); sum += v[q]; }
    }
    #pragma unroll
    for (int o = 16; o > 0; o >>= 1) sum += __shfl_xor_sync(0xffffffffu, sum, o);
    float inv = 1.f / sum;
    cnt = 0;
    for (int j = lane; j < N; j += 32) p[j] = v[cnt++] * inv;
}

// =====================================================================
// Batched attention, stage 3: O = P @ V per (b,h). Writes bf16 pair.
// =====================================================================
__global__ __launch_bounds__(256)
void attn_pv_kernel(const float* __restrict__ att, const float* __restrict__ qkv,
                    bf16* __restrict__ oh, bf16* __restrict__ ol, int N)
{
    __shared__ __align__(16) float Ph[64][SK];
    __shared__ __align__(16) float Pl[64][SK];
    __shared__ __align__(16) float Vh[64][SK];   // [d][j]
    __shared__ __align__(16) float Vl[64][SK];

    int tid = threadIdx.x;
    int lane = tid & 31, w = tid >> 5;
    int wm = w >> 2, wn = w & 3;
    int g = lane >> 2, tig = lane & 3;
    int bh = blockIdx.z;
    int b = bh / NHD, h = bh % NHD;
    const float* P = att + (size_t)bh*N*N;
    const float* V = qkv + (size_t)b*N*2304 + 1536 + h*HD;
    size_t cbase = (size_t)b*N*DD + h*HD;
    int row0 = blockIdx.y * 64;

    float acc[2][2][4];
    #pragma unroll
    for (int i = 0; i < 2; i++)
        #pragma unroll
        for (int j = 0; j < 2; j++)
            #pragma unroll
            for (int q = 0; q < 4; q++) acc[i][j][q] = 0.f;

    const float4 z4 = make_float4(0.f, 0.f, 0.f, 0.f);
    int pr = tid >> 2;
    int pc = (tid & 3) * 4;
    int vj = tid >> 4;
    int vd = (tid & 15) * 4;

    int ktiles = (N + 15) >> 4;
    for (int kt = 0; kt < ktiles; kt++) {
        int j0 = kt * 16;
        {
            int gi = row0 + pr;
            float pv[4], ph[4], pl[4];
            #pragma unroll
            for (int q = 0; q < 4; q++) {
                int jj = j0 + pc + q;
                pv[q] = (gi < N && jj < N) ? P[(size_t)gi*N + jj] : 0.f;
                uint32_t hh = f2tf(pv[q]);
                ph[q] = __uint_as_float(hh);
                pl[q] = pv[q] - ph[q];
            }
            *(float4*)&Ph[pr][pc] = make_float4(ph[0], ph[1], ph[2], ph[3]);
            *(float4*)&Pl[pr][pc] = make_float4(pl[0], pl[1], pl[2], pl[3]);
        }
        {
            int jj = j0 + vj;
            float4 vv = (jj < N) ? *(const float4*)(V + (size_t)jj*2304 + vd) : z4;
            float vvv[4] = {vv.x, vv.y, vv.z, vv.w};
            #pragma unroll
            for (int q = 0; q < 4; q++) {
                uint32_t hh = f2tf(vvv[q]);
                float hf = __uint_as_float(hh);
                Vh[vd + q][vj] = hf;
                Vl[vd + q][vj] = vvv[q] - hf;
            }
        }
        __syncthreads();
        #pragma unroll
        for (int ks = 0; ks < 2; ks++) {
            int k = ks*8 + tig;
            uint32_t bhf[2][2], blf[2][2];
            #pragma unroll
            for (int nt = 0; nt < 2; nt++) {
                int n = wn*16 + nt*8 + g;
                bhf[nt][0] = __float_as_uint(Vh[n][k]);
                bhf[nt][1] = __float_as_uint(Vh[n][k+4]);
                blf[nt][0] = __float_as_uint(Vl[n][k]);
                blf[nt][1] = __float_as_uint(Vl[n][k+4]);
            }
            #pragma unroll
            for (int mt = 0; mt < 2; mt++) {
                int r = wm*32 + mt*16 + g;
                uint32_t ah[4], al[4];
                ah[0] = __float_as_uint(Ph[r][k]);
                ah[1] = __float_as_uint(Ph[r+8][k]);
                ah[2] = __float_as_uint(Ph[r][k+4]);
                ah[3] = __float_as_uint(Ph[r+8][k+4]);
                al[0] = __float_as_uint(Pl[r][k]);
                al[1] = __float_as_uint(Pl[r+8][k]);
                al[2] = __float_as_uint(Pl[r][k+4]);
                al[3] = __float_as_uint(Pl[r+8][k+4]);
                #pragma unroll
                for (int nt = 0; nt < 2; nt++) {
                    mma_tf32(acc[mt][nt], al, bhf[nt]);
                    mma_tf32(acc[mt][nt], ah, blf[nt]);
                    mma_tf32(acc[mt][nt], ah, bhf[nt]);
                }
            }
        }
        __syncthreads();
    }

    #pragma unroll
    for (int mt = 0; mt < 2; mt++) {
        #pragma unroll
        for (int nt = 0; nt < 2; nt++) {
            int gc0 = wn*16 + nt*8 + 2*tig;
            #pragma unroll
            for (int half = 0; half < 2; half++) {
                int gr = row0 + wm*32 + mt*16 + g + half*8;
                if (gr >= N) continue;
                uint32_t hw, lw2;
                split2_bf16(acc[mt][nt][half*2], acc[mt][nt][half*2 + 1], hw, lw2);
                size_t off = cbase + (size_t)gr*DD + gc0;
                *(uint32_t*)(oh + off) = hw;
                *(uint32_t*)(ol + off) = lw2;
            }
        }
    }
}

// ---------------- SIMT GEMM (tiny shapes: N=1 predictor head, class head) -------
__global__ void gemm_kernel(const float* __restrict__ A, const float* __restrict__ W,
                            const float* __restrict__ bias, const float* __restrict__ resid,
                            float* __restrict__ C, int M, int N, int K, int act)
{
    __shared__ float As[16][65];
    __shared__ float Ws[16][65];
    int tx = threadIdx.x, ty = threadIdx.y;
    int tid = ty*16 + tx;
    int row0 = blockIdx.y*64, col0 = blockIdx.x*64;
    float acc[4][4] = {};
    for (int k0 = 0; k0 < K; k0 += 16) {
        #pragma unroll
        for (int i = 0; i < 4; i++) {
            int idx = tid + i*256;
            int r = idx >> 4;
            int c = idx & 15;
            int gr = row0 + r;
            As[c][r] = (gr < M) ? A[(size_t)gr*K + k0 + c] : 0.f;
            int wr = col0 + r;
            Ws[c][r] = (wr < N) ? W[(size_t)wr*K + k0 + c] : 0.f;
        }
        __syncthreads();
        #pragma unroll
        for (int kk = 0; kk < 16; kk++) {
            float a[4], bb[4];
            #pragma unroll
            for (int i = 0; i < 4; i++) a[i] = As[kk][ty*4+i];
            #pragma unroll
            for (int j = 0; j < 4; j++) bb[j] = Ws[kk][tx*4+j];
            #pragma unroll
            for (int i = 0; i < 4; i++)
                #pragma unroll
                for (int j = 0; j < 4; j++)
                    acc[i][j] = fmaf(a[i], bb[j], acc[i][j]);
        }
        __syncthreads();
    }
    #pragma unroll
    for (int i = 0; i < 4; i++) {
        int gr = row0 + ty*4 + i;
        if (gr >= M) continue;
        #pragma unroll
        for (int j = 0; j < 4; j++) {
            int gc = col0 + tx*4 + j;
            if (gc >= N) continue;
            float v = acc[i][j] + bias[gc];
            if (act == 1) v = gelu_f(v);
            if (resid) v += resid[(size_t)gr*N + gc];
            C[(size_t)gr*N + gc] = v;
        }
    }
}

// ---------------- LayerNorm: out = fp32 (dstf) or bf16 pair (dsth/dstl) --------
__global__ void ln_kernel(const float* __restrict__ src, float* __restrict__ dstf,
                          bf16* __restrict__ dsth, bf16* __restrict__ dstl,
                          const float* __restrict__ gamma, const float* __restrict__ beta,
                          int n_src_tokens, int toks_out, int tok_off)
{
    int r = blockIdx.x;
    int b = r / toks_out;
    int n = r % toks_out + tok_off;
    const float* x = src + ((size_t)b*n_src_tokens + n)*DD;
    int tid = threadIdx.x;                 // 256
    float v[3];
    float s = 0.f, s2 = 0.f;
    #pragma unroll
    for (int i = 0; i < 3; i++) { v[i] = x[tid + i*256]; s += v[i]; s2 += v[i]*v[i]; }
    __shared__ float sh1[8], sh2[8];
    #pragma unroll
    for (int o = 16; o > 0; o >>= 1) {
        s  += __shfl_xor_sync(0xffffffffu, s,  o);
        s2 += __shfl_xor_sync(0xffffffffu, s2, o);
    }
    if ((tid & 31) == 0) { sh1[tid>>5] = s; sh2[tid>>5] = s2; }
    __syncthreads();
    float ts = 0.f, ts2 = 0.f;
    #pragma unroll
    for (int w = 0; w < 8; w++) { ts += sh1[w]; ts2 += sh2[w]; }
    float mean = ts * (1.f/768.f);
    float var  = ts2 * (1.f/768.f) - mean*mean;
    float rstd = rsqrtf(var + 1e-6f);
    size_t ob = (size_t)r*DD;
    #pragma unroll
    for (int i = 0; i < 3; i++) {
        int c = tid + i*256;
        float y = (v[i] - mean) * rstd * gamma[c] + beta[c];
        if (dstf) dstf[ob + c] = y;
        else      split1(y, dsth[ob + c], dstl[ob + c]);
    }
}

// ---------------- predictor helpers ----------------
__global__ void globmean_kernel(const float* __restrict__ hidden, float* __restrict__ glob, int L)
{
    int b = blockIdx.x;
    int c = threadIdx.x;                   // 384
    float s = 0.f;
    for (int l = 0; l < L; l++) s += hidden[((size_t)b*L + l)*DD + 384 + c];
    glob[b*384 + c] = s / (float)L;
}

// combine -> bf16 pair
__global__ void combine_kernel(const float* __restrict__ hidden, const float* __restrict__ glob,
                               bf16* __restrict__ h2h, bf16* __restrict__ h2l, int L)
{
    int i = blockIdx.x * blockDim.x + threadIdx.x;
    int total = BB*L*DD;
    if (i >= total) return;
    int c = i % DD;
    int r = i / DD;
    int b = r / L;
    float v = (c < 384) ? hidden[i] : glob[b*384 + (c - 384)];
    split1(v, h2h[i], h2l[i]);
}

// exact jax top_k order via rank counting (score desc, index asc tie-break).
__global__ void topk_kernel(const float* __restrict__ score, int* __restrict__ idx, int L, int k)
{
    int b = blockIdx.x;
    __shared__ float s[LMAX];
    int t = threadIdx.x;                   // 256
    for (int j = t; j < L; j += blockDim.x) s[j] = score[b*L + j];
    __syncthreads();
    if (t < L) {
        float my = s[t];
        int rank = 0;
        for (int j = 0; j < L; j++) {
            float v = s[j];
            rank += (v > my) || (v == my && j < t);
        }
        if (rank < k) idx[b*LMAX + rank] = t;
    }
}

__global__ void gather_kernel(const float* __restrict__ tin, const int* __restrict__ idx,
                              float* __restrict__ tout, int Nin, int Nout)
{
    int i = blockIdx.x * blockDim.x + threadIdx.x;
    int total = BB*Nout*DD;
    if (i >= total) return;
    int c = i % DD;
    int r = i / DD;
    int b = r / Nout;
    int j = r % Nout;
    int n = (j == 0) ? 0 : (1 + idx[b*LMAX + (j - 1)]);
    tout[i] = tin[((size_t)b*Nin + n)*DD + c];
}

// ---------------- host orchestration ----------------
static inline void launch_gemm2(const bf16* Ah, const bf16* Al,
                                const bf16* Wh, const bf16* Wl,
                                const float* bias, const float* resid,
                                float* Cf, bf16* Ch, bf16* Cl,
                                int M, int N, int K, int act)
{
    dim3 grid((N + 127) / 128, (M + 127) / 128);
    gemm_tc2_kernel<<<grid, 256, GEMM_SMEM_BYTES>>>(Ah, Al, Wh, Wl, bias, resid,
                                                    Cf, Ch, Cl, M, N, K, act);
}

static inline void launch_gemm(const float* A, const float* W, const float* bias,
                               const float* resid, float* C, int M, int N, int K, int act)
{
    dim3 grid((N + 63) / 64, (M + 63) / 64);
    dim3 block(16, 16);
    gemm_kernel<<<grid, block>>>(A, W, bias, resid, C, M, N, K, act);
}

static inline void launch_split(const float* in, bf16* hi, bf16* lo, int n)
{
    int n4 = n / 4;
    split_kernel<<<(n4 + 255) / 256, 256>>>(in, hi, lo, n4);
}

extern "C" void kernel_launch(void* const* d_in, const int* in_sizes, int n_in,
                              void* d_out, int out_size)
{
    const float* x       = (const float*)d_in[0];
    const float* patch_w = (const float*)d_in[1];
    const float* patch_b = (const float*)d_in[2];
    const float* cls_tok = (const float*)d_in[3];
    const float* pos     = (const float*)d_in[4];
    const float* ln1_g   = (const float*)d_in[5];
    const float* ln1_b   = (const float*)d_in[6];
    const float* qkv_w   = (const float*)d_in[7];
    const float* qkv_b   = (const float*)d_in[8];
    const float* proj_w  = (const float*)d_in[9];
    const float* proj_b  = (const float*)d_in[10];
    const float* ln2_g   = (const float*)d_in[11];
    const float* ln2_b   = (const float*)d_in[12];
    const float* fc1_w   = (const float*)d_in[13];
    const float* fc1_b   = (const float*)d_in[14];
    const float* fc2_w   = (const float*)d_in[15];
    const float* fc2_b   = (const float*)d_in[16];
    const float* pln_g   = (const float*)d_in[17];
    const float* pln_b   = (const float*)d_in[18];
    const float* pin_w   = (const float*)d_in[19];
    const float* pin_b   = (const float*)d_in[20];
    const float* pw1     = (const float*)d_in[21];
    const float* pb1     = (const float*)d_in[22];
    const float* pw2     = (const float*)d_in[23];
    const float* pb2     = (const float*)d_in[24];
    const float* pw3     = (const float*)d_in[25];
    const float* pb3     = (const float*)d_in[26];
    const float* norm_g  = (const float*)d_in[27];
    const float* norm_b  = (const float*)d_in[28];
    const float* head_w  = (const float*)d_in[29];
    const float* head_b  = (const float*)d_in[30];
    (void)in_sizes; (void)n_in; (void)out_size;

    cudaFuncSetAttribute(gemm_tc2_kernel,
                         cudaFuncAttributeMaxDynamicSharedMemorySize, GEMM_SMEM_BYTES);

    void* p;
    cudaGetSymbolAddress(&p, g_t0);    float* t0    = (float*)p;
    cudaGetSymbolAddress(&p, g_t1);    float* t1    = (float*)p;
    cudaGetSymbolAddress(&p, g_qkv);   float* qkvb  = (float*)p;
    cudaGetSymbolAddress(&p, g_pa);    float* pa    = (float*)p;
    cudaGetSymbolAddress(&p, g_pb);    float* pbuf  = (float*)p;
    cudaGetSymbolAddress(&p, g_glob);  float* glob  = (float*)p;
    cudaGetSymbolAddress(&p, g_score); float* score = (float*)p;
    cudaGetSymbolAddress(&p, g_idx);   int*   gidx  = (int*)p;
    cudaGetSymbolAddress(&p, g_cls);   float* clsb  = (float*)p;
    cudaGetSymbolAddress(&p, g_att);   float* attb  = (float*)p;

    cudaGetSymbolAddress(&p, g_lnh);   bf16* lnh  = (bf16*)p;
    cudaGetSymbolAddress(&p, g_lnl);   bf16* lnl  = (bf16*)p;
    cudaGetSymbolAddress(&p, g_aoh);   bf16* aoh  = (bf16*)p;
    cudaGetSymbolAddress(&p, g_aol);   bf16* aol  = (bf16*)p;
    cudaGetSymbolAddress(&p, g_mlph);  bf16* mlph = (bf16*)p;
    cudaGetSymbolAddress(&p, g_mlpl);  bf16* mlpl = (bf16*)p;
    cudaGetSymbolAddress(&p, g_imh);   bf16* imh  = (bf16*)p;
    cudaGetSymbolAddress(&p, g_iml);   bf16* iml  = (bf16*)p;
    cudaGetSymbolAddress(&p, g_ppbh);  bf16* ppbh = (bf16*)p;
    cudaGetSymbolAddress(&p, g_ppbl);  bf16* ppbl = (bf16*)p;

    cudaGetSymbolAddress(&p, g_qkvwh);  bf16* qkvwh  = (bf16*)p;
    cudaGetSymbolAddress(&p, g_qkvwl);  bf16* qkvwl  = (bf16*)p;
    cudaGetSymbolAddress(&p, g_projwh); bf16* projwh = (bf16*)p;
    cudaGetSymbolAddress(&p, g_projwl); bf16* projwl = (bf16*)p;
    cudaGetSymbolAddress(&p, g_fc1wh);  bf16* fc1wh  = (bf16*)p;
    cudaGetSymbolAddress(&p, g_fc1wl);  bf16* fc1wl  = (bf16*)p;
    cudaGetSymbolAddress(&p, g_fc2wh);  bf16* fc2wh  = (bf16*)p;
    cudaGetSymbolAddress(&p, g_fc2wl);  bf16* fc2wl  = (bf16*)p;
    cudaGetSymbolAddress(&p, g_patchwh); bf16* patchwh = (bf16*)p;
    cudaGetSymbolAddress(&p, g_patchwl); bf16* patchwl = (bf16*)p;
    cudaGetSymbolAddress(&p, g_pinwh);  bf16* pinwh  = (bf16*)p;
    cudaGetSymbolAddress(&p, g_pinwl);  bf16* pinwl  = (bf16*)p;
    cudaGetSymbolAddress(&p, g_pw1h);   bf16* pw1h   = (bf16*)p;
    cudaGetSymbolAddress(&p, g_pw1l);   bf16* pw1l   = (bf16*)p;
    cudaGetSymbolAddress(&p, g_pw2h);   bf16* pw2h   = (bf16*)p;
    cudaGetSymbolAddress(&p, g_pw2l);   bf16* pw2l   = (bf16*)p;

    // weight splits (every replay; ~0.2 ms bandwidth-bound)
    launch_split(qkv_w,   qkvwh,  qkvwl,  SZ_QKVW);
    launch_split(proj_w,  projwh, projwl, SZ_PROJW);
    launch_split(fc1_w,   fc1wh,  fc1wl,  SZ_FC1W);
    launch_split(fc2_w,   fc2wh,  fc2wl,  SZ_FC2W);
    launch_split(patch_w, patchwh, patchwl, SZ_PATCHW);
    launch_split(pin_w,   pinwh,  pinwl,  SZ_PINW);
    launch_split(pw1,     pw1h,   pw1l,   SZ_PW1);
    launch_split(pw2,     pw2h,   pw2l,   SZ_PW2);

    // patch embedding
    { int total = BB*LMAX*DD; im2col_kernel<<<(total + 255)/256, 256>>>(x, imh, iml); }
    launch_gemm2(imh, iml, patchwh, patchwl, patch_b, nullptr, pbuf, nullptr, nullptr,
                 BB*LMAX, DD, DD, 0);
    { int total = BB*NMAX*DD; assemble_kernel<<<(total + 255)/256, 256>>>(pbuf, cls_tok, pos, t0); }

    float* ta = t0;
    float* tb = t1;
    int N = NMAX;
    const int kkeep[3] = {138, 97, 68};

    for (int i = 0; i < 12; i++) {
        int s = (i == 3) ? 0 : (i == 6) ? 1 : (i == 9) ? 2 : -1;
        if (s >= 0) {
            int L = N - 1;
            int M = BB * L;
            ln_kernel<<<M, 256>>>(ta, nullptr, imh, iml, pln_g + s*DD, pln_b + s*DD, N, L, 1);
            launch_gemm2(imh, iml, pinwh + (size_t)s*DD*DD, pinwl + (size_t)s*DD*DD,
                         pin_b + s*DD, nullptr, pbuf, nullptr, nullptr, M, DD, DD, 1);
            globmean_kernel<<<BB, 384>>>(pbuf, glob, L);
            { int total = M*DD; combine_kernel<<<(total + 255)/256, 256>>>(pbuf, glob, imh, iml, L); }
            launch_gemm2(imh, iml, pw1h + (size_t)s*384*DD, pw1l + (size_t)s*384*DD,
                         pb1 + s*384, nullptr, nullptr, ppbh, ppbl, M, 384, DD, 1);
            launch_gemm2(ppbh, ppbl, pw2h + (size_t)s*192*384, pw2l + (size_t)s*192*384,
                         pb2 + s*192, nullptr, pa, nullptr, nullptr, M, 192, 384, 1);
            launch_gemm(pa, pw3 + (size_t)s*192, pb3 + s, nullptr, score, M, 1, 192, 0);
            topk_kernel<<<BB, 256>>>(score, gidx, L, kkeep[s]);
            int Nn = kkeep[s] + 1;
            { int total = BB*Nn*DD; gather_kernel<<<(total + 255)/256, 256>>>(ta, gidx, tb, N, Nn); }
            float* tmp = ta; ta = tb; tb = tmp;
            N = Nn;
        }
        int M = BB * N;
        int ntile = (N + 63) / 64;
        ln_kernel<<<M, 256>>>(ta, nullptr, lnh, lnl, ln1_g + i*DD, ln1_b + i*DD, N, N, 0);
        launch_gemm2(lnh, lnl, qkvwh + (size_t)i*2304*DD, qkvwl + (size_t)i*2304*DD,
                     qkv_b + i*2304, nullptr, qkvb, nullptr, nullptr, M, 2304, DD, 0);
        {
            dim3 gqk(ntile, ntile, BB*NHD);
            attn_qk_kernel<<<gqk, 256>>>(qkvb, attb, N);
            int rows = BB*NHD*N;
            attn_softmax_kernel<<<(rows + 3)/4, 128>>>(attb, N, rows);
            dim3 gpv(1, ntile, BB*NHD);
            attn_pv_kernel<<<gpv, 256>>>(attb, qkvb, aoh, aol, N);
        }
        launch_gemm2(aoh, aol, projwh + (size_t)i*DD*DD, projwl + (size_t)i*DD*DD,
                     proj_b + i*DD, ta, tb, nullptr, nullptr, M, DD, DD, 0);
        ln_kernel<<<M, 256>>>(tb, nullptr, lnh, lnl, ln2_g + i*DD, ln2_b + i*DD, N, N, 0);
        launch_gemm2(lnh, lnl, fc1wh + (size_t)i*3072*DD, fc1wl + (size_t)i*3072*DD,
                     fc1_b + i*3072, nullptr, nullptr, mlph, mlpl, M, 3072, DD, 1);
        launch_gemm2(mlph, mlpl, fc2wh + (size_t)i*DD*3072, fc2wl + (size_t)i*DD*3072,
                     fc2_b + i*DD, tb, ta, nullptr, nullptr, M, DD, 3072, 0);
    }

    // final LN on cls token + classification head
    ln_kernel<<<BB, 256>>>(ta, clsb, nullptr, nullptr, norm_g, norm_b, N, 1, 0);
    launch_gemm(clsb, head_w, head_b, nullptr, (float*)d_out, BB, 1000, DD, 0);
}